// round 7
// baseline (speedup 1.0000x reference)
#include <cuda_runtime.h>
#include <cuda_bf16.h>
#include <cstdint>
#include <cstddef>

// ---------------- problem constants ----------------
#define N_NODES 50000
#define N_EDGES 800000
#define DIM     128
#define NEG_SLOPE 0.2f

// ---- SMEM layout: A 64-row tiles + B 128-row tiles, bf16, 272B padded rows ----
#define ROWB      272
#define A_TILE_SZ (64 * ROWB)         // 17408
#define B_TILE_SZ (128 * ROWB)        // 34816
#define AH_OFF    0
#define AL_OFF    A_TILE_SZ
#define BH_OFF    (2 * A_TILE_SZ)
#define BL_OFF    (2 * A_TILE_SZ + B_TILE_SZ)
#define SMEM_TOTAL (2 * A_TILE_SZ + 2 * B_TILE_SZ)   // 104448

#define SCAN_BLK 1024
#define MAX_SB   64

// ---------------- scratch (device globals; no allocs allowed) ----------------
__device__ float g_hq [(size_t)N_NODES * DIM];
__device__ float g_hk [(size_t)N_NODES * DIM];
__device__ float g_agg[(size_t)N_NODES * DIM];
__device__ float g_h1 [(size_t)N_NODES * DIM];
__device__ float g_h2 [(size_t)N_NODES * DIM];
__device__ unsigned g_wpack[9 * 16384];     // 9 x (hi 8192 u32 + lo 8192 u32)
__device__ int g_cnt[N_NODES];
__device__ int g_off[N_NODES + 1];
__device__ int g_cur[N_NODES];
__device__ int g_csrc[N_EDGES];
__device__ int g_bsum[MAX_SB];

__device__ __forceinline__ float leakyf(float x) { return x >= 0.f ? x : NEG_SLOPE * x; }

static __device__ __forceinline__ unsigned pack_bf2(float a, float b) {
    __nv_bfloat162 h = __floats2bfloat162_rn(a, b);
    return *(unsigned*)&h;
}

static __device__ __forceinline__ uint32_t smem_u32(const void* p) {
    uint32_t a;
    asm("{ .reg .u64 t; cvta.to.shared.u64 t, %1; cvt.u32.u64 %0, t; }" : "=r"(a) : "l"(p));
    return a;
}

// ---------------- CSR build ----------------
__global__ void zero_int(int* __restrict__ p, int n) {
    int i = blockIdx.x * blockDim.x + threadIdx.x;
    if (i < n) p[i] = 0;
}

__global__ void cnt_kernel(const int* __restrict__ dst, int E, int* __restrict__ cnt) {
    int i = blockIdx.x * blockDim.x + threadIdx.x;
    if (i < E) atomicAdd(&cnt[dst[i]], 1);
}

__global__ void scan_p1(const int* __restrict__ cnt, int* __restrict__ bsum, int n) {
    __shared__ int wsh[8];
    int tid = threadIdx.x;                  // 256 threads
    int base = blockIdx.x * SCAN_BLK;
    int s = 0;
#pragma unroll
    for (int j = 0; j < 4; j++) {
        int i = base + j * 256 + tid;
        if (i < n) s += __ldg(&cnt[i]);
    }
#pragma unroll
    for (int d = 16; d > 0; d >>= 1) s += __shfl_down_sync(0xffffffffu, s, d);
    if ((tid & 31) == 0) wsh[tid >> 5] = s;
    __syncthreads();
    if (tid < 8) {
        int v = wsh[tid];
#pragma unroll
        for (int d = 4; d > 0; d >>= 1) v += __shfl_down_sync(0xffu, v, d);
        if (tid == 0) bsum[blockIdx.x] = v;
    }
}

__global__ void scan_p2(int* __restrict__ bsum, int* __restrict__ off, int nb, int n) {
    int lane = threadIdx.x;                 // 32 threads
    int v0 = (lane < nb)      ? bsum[lane]      : 0;
    int v1 = (32 + lane < nb) ? bsum[32 + lane] : 0;
    int s0 = v0, s1 = v1;
#pragma unroll
    for (int d = 1; d < 32; d <<= 1) {
        int t0 = __shfl_up_sync(0xffffffffu, s0, d);
        int t1 = __shfl_up_sync(0xffffffffu, s1, d);
        if (lane >= d) { s0 += t0; s1 += t1; }
    }
    int tot0 = __shfl_sync(0xffffffffu, s0, 31);
    int tot1 = __shfl_sync(0xffffffffu, s1, 31);
    if (lane < nb)      bsum[lane]      = s0 - v0;
    if (32 + lane < nb) bsum[32 + lane] = tot0 + s1 - v1;
    if (lane == 0) off[n] = tot0 + tot1;
}

__global__ void scan_p3(const int* __restrict__ cnt, const int* __restrict__ bsum,
                        int* __restrict__ off, int* __restrict__ cur, int n) {
    __shared__ int wsh[32];
    int tid = threadIdx.x;                  // 1024 threads
    int lane = tid & 31, w = tid >> 5;
    int i = blockIdx.x * SCAN_BLK + tid;
    int v = (i < n) ? __ldg(&cnt[i]) : 0;
    int s = v;
#pragma unroll
    for (int d = 1; d < 32; d <<= 1) {
        int t = __shfl_up_sync(0xffffffffu, s, d);
        if (lane >= d) s += t;
    }
    if (lane == 31) wsh[w] = s;
    __syncthreads();
    if (w == 0) {
        int x = wsh[lane];
#pragma unroll
        for (int d = 1; d < 32; d <<= 1) {
            int t = __shfl_up_sync(0xffffffffu, x, d);
            if (lane >= d) x += t;
        }
        wsh[lane] = x;
    }
    __syncthreads();
    int excl = s - v + (w ? wsh[w - 1] : 0) + __ldg(&bsum[blockIdx.x]);
    if (i < n) { off[i] = excl; cur[i] = excl; }
}

__global__ void scatter_kernel(const int* __restrict__ src, const int* __restrict__ dst,
                               int E, int* __restrict__ cur, int* __restrict__ csrc) {
    int i = blockIdx.x * blockDim.x + threadIdx.x;
    if (i < E) {
        int pos = atomicAdd(&cur[dst[i]], 1);
        csrc[pos] = src[i];
    }
}

// ---------------- CSR aggregation: warp per dst node, no atomics ----------------
__global__ void agg_csr(const int* __restrict__ off, const int* __restrict__ csrc,
                        const float* __restrict__ hq, const float* __restrict__ hk,
                        float* __restrict__ agg, int N) {
    int warp = (blockIdx.x * blockDim.x + threadIdx.x) >> 5;
    int lane = threadIdx.x & 31;
    if (warp >= N) return;
    int b = __ldg(&off[warp]);
    int e = __ldg(&off[warp + 1]);
    float4 q = __ldg(((const float4*)hq) + (size_t)warp * 32 + lane);
    float4 acc = make_float4(0.f, 0.f, 0.f, 0.f);
    for (int base = b; base < e; base += 32) {
        int s = (base + lane < e) ? __ldg(&csrc[base + lane]) : 0;
        int m = min(32, e - base);
        for (int j = 0; j < m; j++) {
            int sj = __shfl_sync(0xffffffffu, s, j);
            float4 k = __ldg(((const float4*)hk) + (size_t)sj * 32 + lane);
            acc.x += leakyf(q.x + k.x);
            acc.y += leakyf(q.y + k.y);
            acc.z += leakyf(q.z + k.z);
            acc.w += leakyf(q.w + k.w);
        }
    }
    float inv = 1.f / (float)max(e - b, 1);
    ((float4*)agg)[(size_t)warp * 32 + lane] =
        make_float4(acc.x * inv, acc.y * inv, acc.z * inv, acc.w * inv);
}

// ---------------- pack weights: bf16 hi/lo images, layout [n][k] (transposed) ----------------
__global__ void pack_w(const float* __restrict__ Wq, const float* __restrict__ Wk,
                       const float* __restrict__ Wr, const float* __restrict__ Wro) {
    int mat = blockIdx.x;  // 0..8
    const float* W;
    switch (mat) {
        case 0: W = Wq;         break;
        case 1: W = Wk;         break;
        case 2: W = Wr;         break;
        case 3: W = Wq + 16384; break;
        case 4: W = Wk + 16384; break;
        case 5: W = Wr + 16384; break;
        default: W = Wro + (mat - 6) * 16384; break;
    }
    unsigned short* hi = (unsigned short*)(g_wpack + (size_t)mat * 16384);
    unsigned short* lo = (unsigned short*)(g_wpack + (size_t)mat * 16384 + 8192);
    int n  = threadIdx.x & 127;
    int kc = threadIdx.x >> 7;
#pragma unroll
    for (int j = 0; j < 16; j++) {
        int k = kc * 16 + j;
        float w = __ldg(&W[k * 128 + n]);
        __nv_bfloat16 h = __float2bfloat16(w);
        float l = w - __bfloat162float(h);
        __nv_bfloat16 e = __float2bfloat16(l);
        hi[n * 128 + k] = __bfloat16_as_ushort(h);
        lo[n * 128 + k] = __bfloat16_as_ushort(e);
    }
}

// ---------------- GEMM building blocks (256 threads/CTA, 64-row M tiles) ----------------
static __device__ __forceinline__ void conv_A(char* sm, const float* __restrict__ A,
                                              int row0, int N) {
#pragma unroll
    for (int it = 0; it < 8; it++) {
        int idx = it * 256 + threadIdx.x;   // 0..2047
        int r  = idx >> 5;                  // 0..63
        int c4 = idx & 31;
        int gidx = row0 + r;
        int gc = gidx < N ? gidx : N - 1;
        float4 v = __ldg(((const float4*)(A + (size_t)gc * 128)) + c4);
        float hx = __bfloat162float(__float2bfloat16(v.x));
        float hy = __bfloat162float(__float2bfloat16(v.y));
        float hz = __bfloat162float(__float2bfloat16(v.z));
        float hw = __bfloat162float(__float2bfloat16(v.w));
        uint2 hiP = make_uint2(pack_bf2(v.x, v.y), pack_bf2(v.z, v.w));
        uint2 loP = make_uint2(pack_bf2(v.x - hx, v.y - hy), pack_bf2(v.z - hz, v.w - hw));
        *(uint2*)(sm + AH_OFF + r * ROWB + c4 * 8) = hiP;
        *(uint2*)(sm + AL_OFF + r * ROWB + c4 * 8) = loP;
    }
}

static __device__ __forceinline__ void copy_B(char* sm, int widx) {
    const uint4* src = (const uint4*)(g_wpack + (size_t)widx * 16384);
#pragma unroll
    for (int it = 0; it < 8; it++) {
        int i = it * 256 + threadIdx.x;   // 0..2047
        int r = i >> 4, c = i & 15;
        *(uint4*)(sm + BH_OFF + r * ROWB + c * 16) = __ldg(src + i);
        *(uint4*)(sm + BL_OFF + r * ROWB + c * 16) = __ldg(src + 2048 + i);
    }
}

static __device__ __forceinline__ void mma_bf16(float* c, uint32_t a0, uint32_t a1,
                                                uint32_t a2, uint32_t a3,
                                                uint32_t b0, uint32_t b1) {
    asm volatile("mma.sync.aligned.m16n8k16.row.col.f32.bf16.bf16.f32 "
                 "{%0,%1,%2,%3}, {%4,%5,%6,%7}, {%8,%9}, {%0,%1,%2,%3};"
                 : "+f"(c[0]), "+f"(c[1]), "+f"(c[2]), "+f"(c[3])
                 : "r"(a0), "r"(a1), "r"(a2), "r"(a3), "r"(b0), "r"(b1));
}

static __device__ __forceinline__ void ldsm_x4(uint32_t* r, uint32_t addr) {
    asm volatile("ldmatrix.sync.aligned.m8n8.x4.shared.b16 {%0,%1,%2,%3}, [%4];"
                 : "=r"(r[0]), "=r"(r[1]), "=r"(r[2]), "=r"(r[3]) : "r"(addr));
}
static __device__ __forceinline__ void ldsm_x2(uint32_t& r0, uint32_t& r1, uint32_t addr) {
    asm volatile("ldmatrix.sync.aligned.m8n8.x2.shared.b16 {%0,%1}, [%2];"
                 : "=r"(r0), "=r"(r1) : "r"(addr));
}

// warp tile 16(M) x 64(N); 3 split segments: Ah*Wh + Al*Wh + Ah*Wl (ldmatrix feed)
static __device__ __forceinline__ void run_mma(float acc[8][4], const char* sm,
                                               int mbase, int nbase, int lane) {
    uint32_t aoff = (uint32_t)((mbase + (lane & 15)) * ROWB + (lane >> 4) * 16);
    uint32_t boff = (uint32_t)((nbase + (lane & 7)) * ROWB + ((lane >> 3) & 1) * 16);
    uint32_t sbase = smem_u32(sm);
#pragma unroll
    for (int s = 0; s < 3; s++) {
        uint32_t Aa = sbase + (s == 1 ? AL_OFF : AH_OFF) + aoff;
        uint32_t Ba = sbase + (s == 2 ? BL_OFF : BH_OFF) + boff;
#pragma unroll
        for (int ks = 0; ks < 8; ks++) {
            uint32_t kb = ks * 32;
            uint32_t a0[4];
            ldsm_x4(a0, Aa + kb);
#pragma unroll
            for (int nf = 0; nf < 8; nf++) {
                uint32_t b0, b1;
                ldsm_x2(b0, b1, Ba + nf * (8 * ROWB) + kb);
                mma_bf16(acc[nf], a0[0], a0[1], a0[2], a0[3], b0, b1);
            }
        }
    }
}

static __device__ __forceinline__ void zero_acc(float acc[8][4]) {
#pragma unroll
    for (int nf = 0; nf < 8; nf++)
#pragma unroll
        for (int i = 0; i < 4; i++) acc[nf][i] = 0.f;
}

static __device__ __forceinline__ void epi(float acc[8][4], float* __restrict__ out,
                                           int row0, int mbase, int nbase, int g, int t,
                                           const float* b0, const float* b1, const float* b2,
                                           int N, int doLeaky) {
    float bias[8][2];
#pragma unroll
    for (int nf = 0; nf < 8; nf++) {
#pragma unroll
        for (int i = 0; i < 2; i++) {
            int col = nbase + nf * 8 + t * 2 + i;
            float bb = __ldg(&b0[col]);
            if (b1) bb += __ldg(&b1[col]);
            if (b2) bb += __ldg(&b2[col]);
            bias[nf][i] = bb;
        }
    }
#pragma unroll
    for (int half = 0; half < 2; half++) {
        int row = row0 + mbase + g + half * 8;
        if (row < N) {
            float* op = out + (size_t)row * 128;
#pragma unroll
            for (int nf = 0; nf < 8; nf++) {
                float x = acc[nf][half * 2 + 0] + bias[nf][0];
                float y = acc[nf][half * 2 + 1] + bias[nf][1];
                if (doLeaky) { x = leakyf(x); y = leakyf(y); }
                *(float2*)(op + nbase + nf * 8 + t * 2) = make_float2(x, y);
            }
        }
    }
}

// ---------------- fused Q/K GEMM: hq = A@Wq + bq ; hk = A@Wk + bk ----------------
__global__ void __launch_bounds__(256, 2)
gemm_qk(const float* __restrict__ A, int wq, int wk,
        const float* __restrict__ bq, const float* __restrict__ bk,
        float* __restrict__ hq, float* __restrict__ hk, int N) {
    extern __shared__ char sm[];
    int tid = threadIdx.x, w = tid >> 5, lane = tid & 31;
    int g = lane >> 2, t = lane & 3;
    int mbase = (w >> 1) * 16, nbase = (w & 1) * 64;
    int row0 = blockIdx.x * 64;

    conv_A(sm, A, row0, N);
    copy_B(sm, wq);
    __syncthreads();

    float acc[8][4];
    zero_acc(acc);
    run_mma(acc, sm, mbase, nbase, lane);
    epi(acc, hq, row0, mbase, nbase, g, t, bq, nullptr, nullptr, N, 0);

    __syncthreads();
    copy_B(sm, wk);
    __syncthreads();

    zero_acc(acc);
    run_mma(acc, sm, mbase, nbase, lane);
    epi(acc, hk, row0, mbase, nbase, g, t, bk, nullptr, nullptr, N, 0);
}

// ---------------- multi-stage accumulating GEMM ----------------
__global__ void __launch_bounds__(256, 2)
gemm_multi(const float* __restrict__ a0, const float* __restrict__ a1, const float* __restrict__ a2,
           int w0, int w1, int w2,
           const float* __restrict__ b0, const float* __restrict__ b1, const float* __restrict__ b2,
           float* __restrict__ out, int N, int nst, int doLeaky) {
    extern __shared__ char sm[];
    int tid = threadIdx.x, w = tid >> 5, lane = tid & 31;
    int g = lane >> 2, t = lane & 3;
    int mbase = (w >> 1) * 16, nbase = (w & 1) * 64;
    int row0 = blockIdx.x * 64;

    const float* As[3] = {a0, a1, a2};
    int ws[3] = {w0, w1, w2};

    float acc[8][4];
    zero_acc(acc);

    for (int s = 0; s < nst; s++) {
        if (s) __syncthreads();
        conv_A(sm, As[s], row0, N);
        copy_B(sm, ws[s]);
        __syncthreads();
        run_mma(acc, sm, mbase, nbase, lane);
    }

    epi(acc, out, row0, mbase, nbase, g, t, b0, b1, b2, N, doLeaky);
}

// ---------------- launch ----------------
extern "C" void kernel_launch(void* const* d_in, const int* in_sizes, int n_in,
                              void* d_out, int out_size) {
    const float* feats = (const float*)d_in[0];
    const float* Wq    = (const float*)d_in[1];
    const float* bq    = (const float*)d_in[2];
    const float* Wk    = (const float*)d_in[3];
    const float* bk    = (const float*)d_in[4];
    const float* Wr    = (const float*)d_in[5];
    const float* br    = (const float*)d_in[6];
    const float* Wro   = (const float*)d_in[7];
    const float* bro   = (const float*)d_in[8];
    const int*   src   = (const int*)d_in[9];
    const int*   dst   = (const int*)d_in[10];

    int N = in_sizes[0] / DIM;   // 50000
    int E = in_sizes[9];         // 800000
    float* out = (float*)d_out;

    float *hq, *hk, *agg, *h1, *h2;
    int *cnt, *off, *cur, *csrc, *bsum;
    cudaGetSymbolAddress((void**)&hq,   g_hq);
    cudaGetSymbolAddress((void**)&hk,   g_hk);
    cudaGetSymbolAddress((void**)&agg,  g_agg);
    cudaGetSymbolAddress((void**)&h1,   g_h1);
    cudaGetSymbolAddress((void**)&h2,   g_h2);
    cudaGetSymbolAddress((void**)&cnt,  g_cnt);
    cudaGetSymbolAddress((void**)&off,  g_off);
    cudaGetSymbolAddress((void**)&cur,  g_cur);
    cudaGetSymbolAddress((void**)&csrc, g_csrc);
    cudaGetSymbolAddress((void**)&bsum, g_bsum);

    cudaFuncSetAttribute(gemm_qk,    cudaFuncAttributeMaxDynamicSharedMemorySize, SMEM_TOTAL);
    cudaFuncSetAttribute(gemm_multi, cudaFuncAttributeMaxDynamicSharedMemorySize, SMEM_TOTAL);

    int gM = (N + 63) / 64;      // 782
    int gAgg = (N * 32 + 255) / 256;
    int nb = (N + SCAN_BLK - 1) / SCAN_BLK;   // 49

    // weight packing (independent of CSR build)
    pack_w<<<9, 1024>>>(Wq, Wk, Wr, Wro);

    // CSR build (by dst)
    zero_int<<<(N + 255) / 256, 256>>>(cnt, N);
    cnt_kernel<<<(E + 255) / 256, 256>>>(dst, E, cnt);
    scan_p1<<<nb, 256>>>(cnt, bsum, N);
    scan_p2<<<1, 32>>>(bsum, off, nb, N);
    scan_p3<<<nb, SCAN_BLK>>>(cnt, bsum, off, cur, N);
    scatter_kernel<<<(E + 255) / 256, 256>>>(src, dst, E, cur, csrc);

    // ---- layer 0 ----
    gemm_qk<<<gM, 256, SMEM_TOTAL>>>(feats, 0, 1, bq, bk, hq, hk, N);
    agg_csr<<<gAgg, 256>>>(off, csrc, hq, hk, agg, N);
    gemm_multi<<<gM, 256, SMEM_TOTAL>>>(agg, nullptr, nullptr, 2, -1, -1,
                                        br, nullptr, nullptr, h1, N, 1, 1);

    // ---- layer 1 ----
    gemm_qk<<<gM, 256, SMEM_TOTAL>>>(h1, 3, 4, bq + 128, bk + 128, hq, hk, N);
    agg_csr<<<gAgg, 256>>>(off, csrc, hq, hk, agg, N);
    gemm_multi<<<gM, 256, SMEM_TOTAL>>>(agg, nullptr, nullptr, 5, -1, -1,
                                        br + 128, nullptr, nullptr, h2, N, 1, 1);

    // ---- jumping-knowledge readout (3 stages accumulated in registers) ----
    gemm_multi<<<gM, 256, SMEM_TOTAL>>>(feats, h1, h2, 6, 7, 8,
                                        bro, bro + 128, bro + 256, out, N, 3, 0);
}

// round 8
// speedup vs baseline: 1.0691x; 1.0691x over previous
#include <cuda_runtime.h>
#include <cuda_bf16.h>
#include <cstdint>
#include <cstddef>

// ---------------- problem constants ----------------
#define N_NODES 50000
#define N_EDGES 800000
#define DIM     128
#define NEG_SLOPE 0.2f

// ---- SMEM: A hi/lo (128 rows) + two B hi/lo buffers, 272B padded rows ----
#define ROWB      272
#define T_SZ      (128 * ROWB)          // 34816
#define AH_OFF    0
#define AL_OFF    T_SZ
#define B0_OFF    (2 * T_SZ)            // buf0: hi at +0, lo at +T_SZ
#define B1_OFF    (4 * T_SZ)            // buf1: hi at +0, lo at +T_SZ
#define SMEM_TOTAL (6 * T_SZ)           // 208896

#define SCAN_BLK 1024
#define MAX_SB   64

// ---------------- scratch (device globals; no allocs allowed) ----------------
__device__ float g_hq [(size_t)N_NODES * DIM];
__device__ float g_hk [(size_t)N_NODES * DIM];
__device__ float g_agg[(size_t)N_NODES * DIM];
__device__ float g_h1 [(size_t)N_NODES * DIM];
__device__ unsigned g_wpack[9 * 16384];     // 9 x (hi 8192 u32 + lo 8192 u32)
__device__ int g_cnt[N_NODES];
__device__ int g_off[N_NODES + 1];
__device__ int g_cur[N_NODES];
__device__ int g_csrc[N_EDGES];
__device__ int g_bsum[MAX_SB];

__device__ __forceinline__ float leakyf(float x) { return x >= 0.f ? x : NEG_SLOPE * x; }

static __device__ __forceinline__ unsigned pack_bf2(float a, float b) {
    __nv_bfloat162 h = __floats2bfloat162_rn(a, b);
    return *(unsigned*)&h;
}
static __device__ __forceinline__ float bf16r(float x) {
    return __bfloat162float(__float2bfloat16(x));
}
static __device__ __forceinline__ uint32_t smem_u32(const void* p) {
    uint32_t a;
    asm("{ .reg .u64 t; cvta.to.shared.u64 t, %1; cvt.u32.u64 %0, t; }" : "=r"(a) : "l"(p));
    return a;
}
static __device__ __forceinline__ void cp16(uint32_t d, const void* s) {
    asm volatile("cp.async.cg.shared.global [%0], [%1], 16;" :: "r"(d), "l"(s));
}
static __device__ __forceinline__ void cp_commit() {
    asm volatile("cp.async.commit_group;");
}
static __device__ __forceinline__ void cp_wait0() {
    asm volatile("cp.async.wait_group 0;");
}
static __device__ __forceinline__ void cp_wait1() {
    asm volatile("cp.async.wait_group 1;");
}

// ---------------- CSR build ----------------
__global__ void zero_int(int* __restrict__ p, int n) {
    int i = blockIdx.x * blockDim.x + threadIdx.x;
    if (i < n) p[i] = 0;
}
__global__ void cnt_kernel(const int* __restrict__ dst, int E, int* __restrict__ cnt) {
    int i = blockIdx.x * blockDim.x + threadIdx.x;
    if (i < E) atomicAdd(&cnt[dst[i]], 1);
}
__global__ void scan_p1(const int* __restrict__ cnt, int* __restrict__ bsum, int n) {
    __shared__ int wsh[8];
    int tid = threadIdx.x;
    int base = blockIdx.x * SCAN_BLK;
    int s = 0;
#pragma unroll
    for (int j = 0; j < 4; j++) {
        int i = base + j * 256 + tid;
        if (i < n) s += __ldg(&cnt[i]);
    }
#pragma unroll
    for (int d = 16; d > 0; d >>= 1) s += __shfl_down_sync(0xffffffffu, s, d);
    if ((tid & 31) == 0) wsh[tid >> 5] = s;
    __syncthreads();
    if (tid < 8) {
        int v = wsh[tid];
#pragma unroll
        for (int d = 4; d > 0; d >>= 1) v += __shfl_down_sync(0xffu, v, d);
        if (tid == 0) bsum[blockIdx.x] = v;
    }
}
__global__ void scan_p2(int* __restrict__ bsum, int* __restrict__ off, int nb, int n) {
    int lane = threadIdx.x;
    int v0 = (lane < nb)      ? bsum[lane]      : 0;
    int v1 = (32 + lane < nb) ? bsum[32 + lane] : 0;
    int s0 = v0, s1 = v1;
#pragma unroll
    for (int d = 1; d < 32; d <<= 1) {
        int t0 = __shfl_up_sync(0xffffffffu, s0, d);
        int t1 = __shfl_up_sync(0xffffffffu, s1, d);
        if (lane >= d) { s0 += t0; s1 += t1; }
    }
    int tot0 = __shfl_sync(0xffffffffu, s0, 31);
    int tot1 = __shfl_sync(0xffffffffu, s1, 31);
    if (lane < nb)      bsum[lane]      = s0 - v0;
    if (32 + lane < nb) bsum[32 + lane] = tot0 + s1 - v1;
    if (lane == 0) off[n] = tot0 + tot1;
}
__global__ void scan_p3(const int* __restrict__ cnt, const int* __restrict__ bsum,
                        int* __restrict__ off, int* __restrict__ cur, int n) {
    __shared__ int wsh[32];
    int tid = threadIdx.x;
    int lane = tid & 31, w = tid >> 5;
    int i = blockIdx.x * SCAN_BLK + tid;
    int v = (i < n) ? __ldg(&cnt[i]) : 0;
    int s = v;
#pragma unroll
    for (int d = 1; d < 32; d <<= 1) {
        int t = __shfl_up_sync(0xffffffffu, s, d);
        if (lane >= d) s += t;
    }
    if (lane == 31) wsh[w] = s;
    __syncthreads();
    if (w == 0) {
        int x = wsh[lane];
#pragma unroll
        for (int d = 1; d < 32; d <<= 1) {
            int t = __shfl_up_sync(0xffffffffu, x, d);
            if (lane >= d) x += t;
        }
        wsh[lane] = x;
    }
    __syncthreads();
    int excl = s - v + (w ? wsh[w - 1] : 0) + __ldg(&bsum[blockIdx.x]);
    if (i < n) { off[i] = excl; cur[i] = excl; }
}
__global__ void scatter_kernel(const int* __restrict__ src, const int* __restrict__ dst,
                               int E, int* __restrict__ cur, int* __restrict__ csrc) {
    int i = blockIdx.x * blockDim.x + threadIdx.x;
    if (i < E) {
        int pos = atomicAdd(&cur[dst[i]], 1);
        csrc[pos] = src[i];
    }
}

// ---------------- CSR aggregation: warp per dst node, no atomics ----------------
__global__ void agg_csr(const int* __restrict__ off, const int* __restrict__ csrc,
                        const float* __restrict__ hq, const float* __restrict__ hk,
                        float* __restrict__ agg, int N) {
    int warp = (blockIdx.x * blockDim.x + threadIdx.x) >> 5;
    int lane = threadIdx.x & 31;
    if (warp >= N) return;
    int b = __ldg(&off[warp]);
    int e = __ldg(&off[warp + 1]);
    float4 q = __ldg(((const float4*)hq) + (size_t)warp * 32 + lane);
    float4 acc = make_float4(0.f, 0.f, 0.f, 0.f);
    for (int base = b; base < e; base += 32) {
        int s = (base + lane < e) ? __ldg(&csrc[base + lane]) : 0;
        int m = min(32, e - base);
        for (int j = 0; j < m; j++) {
            int sj = __shfl_sync(0xffffffffu, s, j);
            float4 k = __ldg(((const float4*)hk) + (size_t)sj * 32 + lane);
            acc.x += leakyf(q.x + k.x);
            acc.y += leakyf(q.y + k.y);
            acc.z += leakyf(q.z + k.z);
            acc.w += leakyf(q.w + k.w);
        }
    }
    float inv = 1.f / (float)max(e - b, 1);
    ((float4*)agg)[(size_t)warp * 32 + lane] =
        make_float4(acc.x * inv, acc.y * inv, acc.z * inv, acc.w * inv);
}

// ---------------- pack weights: bf16 hi/lo images, layout [n][k] ----------------
__global__ void pack_w(const float* __restrict__ Wq, const float* __restrict__ Wk,
                       const float* __restrict__ Wr, const float* __restrict__ Wro) {
    int mat = blockIdx.x;  // 0..8
    const float* W;
    switch (mat) {
        case 0: W = Wq;         break;
        case 1: W = Wk;         break;
        case 2: W = Wr;         break;
        case 3: W = Wq + 16384; break;
        case 4: W = Wk + 16384; break;
        case 5: W = Wr + 16384; break;
        default: W = Wro + (mat - 6) * 16384; break;
    }
    unsigned short* hi = (unsigned short*)(g_wpack + (size_t)mat * 16384);
    unsigned short* lo = (unsigned short*)(g_wpack + (size_t)mat * 16384 + 8192);
    int n  = threadIdx.x & 127;
    int kc = threadIdx.x >> 7;
#pragma unroll
    for (int j = 0; j < 16; j++) {
        int k = kc * 16 + j;
        float w = __ldg(&W[k * 128 + n]);
        __nv_bfloat16 h = __float2bfloat16(w);
        float l = w - __bfloat162float(h);
        hi[n * 128 + k] = __bfloat16_as_ushort(h);
        lo[n * 128 + k] = __bfloat16_as_ushort(__float2bfloat16(l));
    }
}

// ---------------- GEMM building blocks (256 threads/CTA, 128-row tiles) ----------------
static __device__ __forceinline__ void conv_A(char* sm, const float* __restrict__ A,
                                              int row0, int N) {
#pragma unroll
    for (int it = 0; it < 16; it++) {
        int idx = it * 256 + threadIdx.x;   // 0..4095
        int r  = idx >> 5;
        int c4 = idx & 31;
        int gidx = row0 + r;
        int gc = gidx < N ? gidx : N - 1;
        float4 v = __ldg(((const float4*)(A + (size_t)gc * 128)) + c4);
        float hx = bf16r(v.x), hy = bf16r(v.y), hz = bf16r(v.z), hw = bf16r(v.w);
        *(uint2*)(sm + AH_OFF + r * ROWB + c4 * 8) =
            make_uint2(pack_bf2(v.x, v.y), pack_bf2(v.z, v.w));
        *(uint2*)(sm + AL_OFF + r * ROWB + c4 * 8) =
            make_uint2(pack_bf2(v.x - hx, v.y - hy), pack_bf2(v.z - hz, v.w - hw));
    }
}

// async copy one weight image (hi+lo) into a B buffer; caller commits group
static __device__ __forceinline__ void copy_B_async(uint32_t sbase, int bufOff, int widx) {
    const char* src = (const char*)(g_wpack + (size_t)widx * 16384);
    uint32_t dst = sbase + bufOff;
#pragma unroll
    for (int it = 0; it < 8; it++) {
        int i = it * 256 + threadIdx.x;   // 0..2047
        int r = i >> 4, c = i & 15;
        cp16(dst + r * ROWB + c * 16,        src + i * 16);            // hi
        cp16(dst + T_SZ + r * ROWB + c * 16, src + 32768 + i * 16);    // lo
    }
    cp_commit();
}

static __device__ __forceinline__ void mma_bf16(float* c, uint32_t a0, uint32_t a1,
                                                uint32_t a2, uint32_t a3,
                                                uint32_t b0, uint32_t b1) {
    asm volatile("mma.sync.aligned.m16n8k16.row.col.f32.bf16.bf16.f32 "
                 "{%0,%1,%2,%3}, {%4,%5,%6,%7}, {%8,%9}, {%0,%1,%2,%3};"
                 : "+f"(c[0]), "+f"(c[1]), "+f"(c[2]), "+f"(c[3])
                 : "r"(a0), "r"(a1), "r"(a2), "r"(a3), "r"(b0), "r"(b1));
}
static __device__ __forceinline__ void ldsm_x4(uint32_t* r, uint32_t addr) {
    asm volatile("ldmatrix.sync.aligned.m8n8.x4.shared.b16 {%0,%1,%2,%3}, [%4];"
                 : "=r"(r[0]), "=r"(r[1]), "=r"(r[2]), "=r"(r[3]) : "r"(addr));
}
static __device__ __forceinline__ void ldsm_x2(uint32_t& r0, uint32_t& r1, uint32_t addr) {
    asm volatile("ldmatrix.sync.aligned.m8n8.x2.shared.b16 {%0,%1}, [%2];"
                 : "=r"(r0), "=r"(r1) : "r"(addr));
}

// warp tile 32(M) x 64(N); segments: (AH,BH) + (AL,BH) + (AH,BL)
static __device__ __forceinline__ void run_mma(float acc[2][8][4], uint32_t sbase,
                                               int bufOff, int mbase, int nbase, int lane) {
    uint32_t aoff = (uint32_t)((mbase + (lane & 15)) * ROWB + (lane >> 4) * 16);
    uint32_t boff = (uint32_t)((nbase + (lane & 7)) * ROWB + ((lane >> 3) & 1) * 16);
#pragma unroll
    for (int s = 0; s < 3; s++) {
        uint32_t Aa = sbase + (s == 1 ? AL_OFF : AH_OFF) + aoff;
        uint32_t Ba = sbase + bufOff + (s == 2 ? T_SZ : 0) + boff;
#pragma unroll
        for (int ks = 0; ks < 8; ks++) {
            uint32_t kb = ks * 32;
            uint32_t a0[4], a1[4];
            ldsm_x4(a0, Aa + kb);
            ldsm_x4(a1, Aa + 16 * ROWB + kb);
#pragma unroll
            for (int nf = 0; nf < 8; nf++) {
                uint32_t b0, b1;
                ldsm_x2(b0, b1, Ba + nf * (8 * ROWB) + kb);
                mma_bf16(acc[0][nf], a0[0], a0[1], a0[2], a0[3], b0, b1);
                mma_bf16(acc[1][nf], a1[0], a1[1], a1[2], a1[3], b0, b1);
            }
        }
    }
}

static __device__ __forceinline__ void zero_acc(float acc[2][8][4]) {
#pragma unroll
    for (int mf = 0; mf < 2; mf++)
#pragma unroll
        for (int nf = 0; nf < 8; nf++)
#pragma unroll
            for (int i = 0; i < 4; i++) acc[mf][nf][i] = 0.f;
}

// epilogue: write (doAdd=0) or accumulate (doAdd=1) to out
static __device__ __forceinline__ void epi(float acc[2][8][4], float* __restrict__ out,
                                           int row0, int mbase, int nbase, int g, int t,
                                           const float* b0, const float* b1, const float* b2,
                                           int N, int doAdd) {
    float bias[8][2];
#pragma unroll
    for (int nf = 0; nf < 8; nf++) {
#pragma unroll
        for (int i = 0; i < 2; i++) {
            float bb = 0.f;
            int col = nbase + nf * 8 + t * 2 + i;
            if (b0) bb += __ldg(&b0[col]);
            if (b1) bb += __ldg(&b1[col]);
            if (b2) bb += __ldg(&b2[col]);
            bias[nf][i] = bb;
        }
    }
#pragma unroll
    for (int mf = 0; mf < 2; mf++) {
#pragma unroll
        for (int half = 0; half < 2; half++) {
            int row = row0 + mbase + mf * 16 + g + half * 8;
            if (row < N) {
                float* op = out + (size_t)row * 128 + nbase;
#pragma unroll
                for (int nf = 0; nf < 8; nf++) {
                    float x = acc[mf][nf][half * 2 + 0] + bias[nf][0];
                    float y = acc[mf][nf][half * 2 + 1] + bias[nf][1];
                    float2* p = (float2*)(op + nf * 8 + t * 2);
                    if (doAdd) {
                        float2 o = *p;
                        o.x += x; o.y += y;
                        *p = o;
                    } else {
                        *p = make_float2(x, y);
                    }
                }
            }
        }
    }
}

// h = leaky(acc + br): store into A smem (hi/lo) and optionally gmem
static __device__ __forceinline__ void store_h(float acc[2][8][4], char* sm,
                                               const float* __restrict__ br_,
                                               float* __restrict__ hout,
                                               int row0, int mbase, int nbase,
                                               int g, int t, int N) {
    float bias[8][2];
#pragma unroll
    for (int nf = 0; nf < 8; nf++) {
#pragma unroll
        for (int i = 0; i < 2; i++)
            bias[nf][i] = __ldg(&br_[nbase + nf * 8 + t * 2 + i]);
    }
#pragma unroll
    for (int mf = 0; mf < 2; mf++) {
#pragma unroll
        for (int half = 0; half < 2; half++) {
            int rl = mbase + mf * 16 + g + half * 8;
            int row = row0 + rl;
#pragma unroll
            for (int nf = 0; nf < 8; nf++) {
                float x = leakyf(acc[mf][nf][half * 2 + 0] + bias[nf][0]);
                float y = leakyf(acc[mf][nf][half * 2 + 1] + bias[nf][1]);
                int c = nbase + nf * 8 + t * 2;
                float hx = bf16r(x), hy = bf16r(y);
                *(unsigned*)(sm + AH_OFF + rl * ROWB + c * 2) = pack_bf2(x, y);
                *(unsigned*)(sm + AL_OFF + rl * ROWB + c * 2) = pack_bf2(x - hx, y - hy);
                if (hout && row < N)
                    *(float2*)(hout + (size_t)row * 128 + c) = make_float2(x, y);
            }
        }
    }
}

// ---------------- kernel 1/3: hq = A@Wq+bq ; hk = A@Wk+bk ; [out = A@Wro+bro_sum] ----------------
__global__ void __launch_bounds__(256, 1)
gemm_qk3(const float* __restrict__ A, int wq, int wk, int wo,
         const float* __restrict__ bq, const float* __restrict__ bk,
         const float* __restrict__ bro,   // base of bro (3x128) or null
         float* __restrict__ hq, float* __restrict__ hk, float* __restrict__ out, int N) {
    extern __shared__ char sm[];
    uint32_t sbase = smem_u32(sm);
    int tid = threadIdx.x, w = tid >> 5, lane = tid & 31;
    int g = lane >> 2, t = lane & 3;
    int mbase = (w >> 1) * 32, nbase = (w & 1) * 64;
    int row0 = blockIdx.x * 128;

    copy_B_async(sbase, B0_OFF, wq);      // group 1
    conv_A(sm, A, row0, N);
    copy_B_async(sbase, B1_OFF, wk);      // group 2

    cp_wait1();                            // buf0 ready
    __syncthreads();

    float acc[2][8][4];
    zero_acc(acc);
    run_mma(acc, sbase, B0_OFF, mbase, nbase, lane);
    epi(acc, hq, row0, mbase, nbase, g, t, bq, nullptr, nullptr, N, 0);

    cp_wait0();                            // buf1 ready
    __syncthreads();                       // everyone done with buf0
    if (wo >= 0) copy_B_async(sbase, B0_OFF, wo);   // group 3 (into buf0)

    zero_acc(acc);
    run_mma(acc, sbase, B1_OFF, mbase, nbase, lane);
    epi(acc, hk, row0, mbase, nbase, g, t, bk, nullptr, nullptr, N, 0);

    if (wo >= 0) {
        cp_wait0();
        __syncthreads();
        zero_acc(acc);
        run_mma(acc, sbase, B0_OFF, mbase, nbase, lane);
        epi(acc, out, row0, mbase, nbase, g, t, bro, bro + 128, bro + 256, N, 0);
    }
}

// ---------------- kernel 2/4: h = leaky(agg@Wr+br) [-> hout]; out += h@Wro ----------------
__global__ void __launch_bounds__(256, 1)
gemm_wr_ro(const float* __restrict__ agg, int wr, int wro,
           const float* __restrict__ br_, float* __restrict__ hout,
           float* __restrict__ out, int N) {
    extern __shared__ char sm[];
    uint32_t sbase = smem_u32(sm);
    int tid = threadIdx.x, w = tid >> 5, lane = tid & 31;
    int g = lane >> 2, t = lane & 3;
    int mbase = (w >> 1) * 32, nbase = (w & 1) * 64;
    int row0 = blockIdx.x * 128;

    copy_B_async(sbase, B0_OFF, wr);      // group 1
    conv_A(sm, agg, row0, N);
    copy_B_async(sbase, B1_OFF, wro);     // group 2

    cp_wait1();
    __syncthreads();

    float acc[2][8][4];
    zero_acc(acc);
    run_mma(acc, sbase, B0_OFF, mbase, nbase, lane);

    __syncthreads();                       // all warps done reading A
    store_h(acc, sm, br_, hout, row0, mbase, nbase, g, t, N);
    cp_wait0();                            // buf1 (Wro) ready
    __syncthreads();                       // h tiles visible to all

    zero_acc(acc);
    run_mma(acc, sbase, B1_OFF, mbase, nbase, lane);
    epi(acc, out, row0, mbase, nbase, g, t, nullptr, nullptr, nullptr, N, 1);
}

// ---------------- launch ----------------
extern "C" void kernel_launch(void* const* d_in, const int* in_sizes, int n_in,
                              void* d_out, int out_size) {
    const float* feats = (const float*)d_in[0];
    const float* Wq    = (const float*)d_in[1];
    const float* bq    = (const float*)d_in[2];
    const float* Wk    = (const float*)d_in[3];
    const float* bk    = (const float*)d_in[4];
    const float* Wr    = (const float*)d_in[5];
    const float* br    = (const float*)d_in[6];
    const float* Wro   = (const float*)d_in[7];
    const float* bro   = (const float*)d_in[8];
    const int*   src   = (const int*)d_in[9];
    const int*   dst   = (const int*)d_in[10];

    int N = in_sizes[0] / DIM;   // 50000
    int E = in_sizes[9];         // 800000
    float* out = (float*)d_out;

    float *hq, *hk, *agg, *h1;
    int *cnt, *off, *cur, *csrc, *bsum;
    cudaGetSymbolAddress((void**)&hq,   g_hq);
    cudaGetSymbolAddress((void**)&hk,   g_hk);
    cudaGetSymbolAddress((void**)&agg,  g_agg);
    cudaGetSymbolAddress((void**)&h1,   g_h1);
    cudaGetSymbolAddress((void**)&cnt,  g_cnt);
    cudaGetSymbolAddress((void**)&off,  g_off);
    cudaGetSymbolAddress((void**)&cur,  g_cur);
    cudaGetSymbolAddress((void**)&csrc, g_csrc);
    cudaGetSymbolAddress((void**)&bsum, g_bsum);

    cudaFuncSetAttribute(gemm_qk3,   cudaFuncAttributeMaxDynamicSharedMemorySize, SMEM_TOTAL);
    cudaFuncSetAttribute(gemm_wr_ro, cudaFuncAttributeMaxDynamicSharedMemorySize, SMEM_TOTAL);

    int gM = (N + 127) / 128;    // 391
    int gAgg = (N * 32 + 255) / 256;
    int nb = (N + SCAN_BLK - 1) / SCAN_BLK;

    // weight packing
    pack_w<<<9, 1024>>>(Wq, Wk, Wr, Wro);

    // CSR build (by dst)
    zero_int<<<(N + 255) / 256, 256>>>(cnt, N);
    cnt_kernel<<<(E + 255) / 256, 256>>>(dst, E, cnt);
    scan_p1<<<nb, 256>>>(cnt, bsum, N);
    scan_p2<<<1, 32>>>(bsum, off, nb, N);
    scan_p3<<<nb, SCAN_BLK>>>(cnt, bsum, off, cur, N);
    scatter_kernel<<<(E + 255) / 256, 256>>>(src, dst, E, cur, csrc);

    // ---- layer 0 (+ readout stage 0 with all biases folded) ----
    gemm_qk3<<<gM, 256, SMEM_TOTAL>>>(feats, 0, 1, 6, bq, bk, bro, hq, hk, out, N);
    agg_csr<<<gAgg, 256>>>(off, csrc, hq, hk, agg, N);
    gemm_wr_ro<<<gM, 256, SMEM_TOTAL>>>(agg, 2, 7, br, h1, out, N);   // h1 + readout 1

    // ---- layer 1 (+ readout stage 2; h2 never hits gmem) ----
    gemm_qk3<<<gM, 256, SMEM_TOTAL>>>(h1, 3, 4, -1, bq + 128, bk + 128, nullptr,
                                      hq, hk, nullptr, N);
    agg_csr<<<gAgg, 256>>>(off, csrc, hq, hk, agg, N);
    gemm_wr_ro<<<gM, 256, SMEM_TOTAL>>>(agg, 5, 8, br + 128, nullptr, out, N);
}

// round 9
// speedup vs baseline: 1.1143x; 1.0423x over previous
#include <cuda_runtime.h>
#include <cuda_bf16.h>
#include <cstdint>
#include <cstddef>

// ---------------- problem constants ----------------
#define N_NODES 50000
#define N_EDGES 800000
#define DIM     128
#define NEG_SLOPE 0.2f

// ---- SMEM: A hi/lo (128 rows) + two B hi/lo buffers, 272B padded rows ----
#define ROWB      272
#define T_SZ      (128 * ROWB)          // 34816
#define AH_OFF    0
#define AL_OFF    T_SZ
#define B0_OFF    (2 * T_SZ)            // buf0: hi at +0, lo at +T_SZ
#define B1_OFF    (4 * T_SZ)            // buf1: hi at +0, lo at +T_SZ
#define SMEM_TOTAL (6 * T_SZ)           // 208896

#define SCAN_BLK 1024
#define MAX_SB   64

// ---------------- scratch (device globals; no allocs allowed) ----------------
__device__ float g_hq [(size_t)N_NODES * DIM];
__device__ float g_hk [(size_t)N_NODES * DIM];
__device__ float g_agg[(size_t)N_NODES * DIM];
__device__ float g_h1 [(size_t)N_NODES * DIM];
__device__ unsigned g_wpack[9 * 16384];     // 9 x (hi 8192 u32 + lo 8192 u32)
__device__ int g_cnt[N_NODES];
__device__ int g_off[N_NODES + 1];
__device__ int g_cur[N_NODES];
__device__ int g_csrc[N_EDGES];
__device__ int g_bsum[MAX_SB];

__device__ __forceinline__ float leakyf(float x) { return x >= 0.f ? x : NEG_SLOPE * x; }

static __device__ __forceinline__ unsigned pack_bf2(float a, float b) {
    __nv_bfloat162 h = __floats2bfloat162_rn(a, b);
    return *(unsigned*)&h;
}
static __device__ __forceinline__ float bf16r(float x) {
    return __bfloat162float(__float2bfloat16(x));
}
static __device__ __forceinline__ uint32_t smem_u32(const void* p) {
    uint32_t a;
    asm("{ .reg .u64 t; cvta.to.shared.u64 t, %1; cvt.u32.u64 %0, t; }" : "=r"(a) : "l"(p));
    return a;
}
static __device__ __forceinline__ void cp16(uint32_t d, const void* s) {
    asm volatile("cp.async.cg.shared.global [%0], [%1], 16;" :: "r"(d), "l"(s));
}
static __device__ __forceinline__ void cp_commit() {
    asm volatile("cp.async.commit_group;");
}
static __device__ __forceinline__ void cp_wait0() {
    asm volatile("cp.async.wait_group 0;");
}
static __device__ __forceinline__ void cp_wait1() {
    asm volatile("cp.async.wait_group 1;");
}

// ---------------- CSR build ----------------
__global__ void zero_int(int* __restrict__ p, int n) {
    int i = blockIdx.x * blockDim.x + threadIdx.x;
    if (i < n) p[i] = 0;
}
__global__ void cnt_kernel(const int* __restrict__ dst, int E, int* __restrict__ cnt) {
    int i = blockIdx.x * blockDim.x + threadIdx.x;
    if (i < E) atomicAdd(&cnt[dst[i]], 1);
}
__global__ void scan_p1(const int* __restrict__ cnt, int* __restrict__ bsum, int n) {
    __shared__ int wsh[8];
    int tid = threadIdx.x;
    int base = blockIdx.x * SCAN_BLK;
    int s = 0;
#pragma unroll
    for (int j = 0; j < 4; j++) {
        int i = base + j * 256 + tid;
        if (i < n) s += __ldg(&cnt[i]);
    }
#pragma unroll
    for (int d = 16; d > 0; d >>= 1) s += __shfl_down_sync(0xffffffffu, s, d);
    if ((tid & 31) == 0) wsh[tid >> 5] = s;
    __syncthreads();
    if (tid < 8) {
        int v = wsh[tid];
#pragma unroll
        for (int d = 4; d > 0; d >>= 1) v += __shfl_down_sync(0xffu, v, d);
        if (tid == 0) bsum[blockIdx.x] = v;
    }
}
__global__ void scan_p2(int* __restrict__ bsum, int* __restrict__ off, int nb, int n) {
    int lane = threadIdx.x;
    int v0 = (lane < nb)      ? bsum[lane]      : 0;
    int v1 = (32 + lane < nb) ? bsum[32 + lane] : 0;
    int s0 = v0, s1 = v1;
#pragma unroll
    for (int d = 1; d < 32; d <<= 1) {
        int t0 = __shfl_up_sync(0xffffffffu, s0, d);
        int t1 = __shfl_up_sync(0xffffffffu, s1, d);
        if (lane >= d) { s0 += t0; s1 += t1; }
    }
    int tot0 = __shfl_sync(0xffffffffu, s0, 31);
    int tot1 = __shfl_sync(0xffffffffu, s1, 31);
    if (lane < nb)      bsum[lane]      = s0 - v0;
    if (32 + lane < nb) bsum[32 + lane] = tot0 + s1 - v1;
    if (lane == 0) off[n] = tot0 + tot1;
}
__global__ void scan_p3(const int* __restrict__ cnt, const int* __restrict__ bsum,
                        int* __restrict__ off, int* __restrict__ cur, int n) {
    __shared__ int wsh[32];
    int tid = threadIdx.x;
    int lane = tid & 31, w = tid >> 5;
    int i = blockIdx.x * SCAN_BLK + tid;
    int v = (i < n) ? __ldg(&cnt[i]) : 0;
    int s = v;
#pragma unroll
    for (int d = 1; d < 32; d <<= 1) {
        int t = __shfl_up_sync(0xffffffffu, s, d);
        if (lane >= d) s += t;
    }
    if (lane == 31) wsh[w] = s;
    __syncthreads();
    if (w == 0) {
        int x = wsh[lane];
#pragma unroll
        for (int d = 1; d < 32; d <<= 1) {
            int t = __shfl_up_sync(0xffffffffu, x, d);
            if (lane >= d) x += t;
        }
        wsh[lane] = x;
    }
    __syncthreads();
    int excl = s - v + (w ? wsh[w - 1] : 0) + __ldg(&bsum[blockIdx.x]);
    if (i < n) { off[i] = excl; cur[i] = excl; }
}
__global__ void scatter_kernel(const int* __restrict__ src, const int* __restrict__ dst,
                               int E, int* __restrict__ cur, int* __restrict__ csrc) {
    int i = blockIdx.x * blockDim.x + threadIdx.x;
    if (i < E) {
        int pos = atomicAdd(&cur[dst[i]], 1);
        csrc[pos] = src[i];
    }
}

// ---------------- CSR aggregation: warp per dst node, no atomics ----------------
__global__ void agg_csr(const int* __restrict__ off, const int* __restrict__ csrc,
                        const float* __restrict__ hq, const float* __restrict__ hk,
                        float* __restrict__ agg, int N) {
    int warp = (blockIdx.x * blockDim.x + threadIdx.x) >> 5;
    int lane = threadIdx.x & 31;
    if (warp >= N) return;
    int b = __ldg(&off[warp]);
    int e = __ldg(&off[warp + 1]);
    float4 q = __ldg(((const float4*)hq) + (size_t)warp * 32 + lane);
    float4 acc = make_float4(0.f, 0.f, 0.f, 0.f);
    for (int base = b; base < e; base += 32) {
        int s = (base + lane < e) ? __ldg(&csrc[base + lane]) : 0;
        int m = min(32, e - base);
        for (int j = 0; j < m; j++) {
            int sj = __shfl_sync(0xffffffffu, s, j);
            float4 k = __ldg(((const float4*)hk) + (size_t)sj * 32 + lane);
            acc.x += leakyf(q.x + k.x);
            acc.y += leakyf(q.y + k.y);
            acc.z += leakyf(q.z + k.z);
            acc.w += leakyf(q.w + k.w);
        }
    }
    float inv = 1.f / (float)max(e - b, 1);
    ((float4*)agg)[(size_t)warp * 32 + lane] =
        make_float4(acc.x * inv, acc.y * inv, acc.z * inv, acc.w * inv);
}

// ---------------- pack weights: bf16 hi/lo images, layout [n][k] ----------------
__global__ void pack_w(const float* __restrict__ Wq, const float* __restrict__ Wk,
                       const float* __restrict__ Wr, const float* __restrict__ Wro) {
    int mat = blockIdx.x;  // 0..8
    const float* W;
    switch (mat) {
        case 0: W = Wq;         break;
        case 1: W = Wk;         break;
        case 2: W = Wr;         break;
        case 3: W = Wq + 16384; break;
        case 4: W = Wk + 16384; break;
        case 5: W = Wr + 16384; break;
        default: W = Wro + (mat - 6) * 16384; break;
    }
    unsigned short* hi = (unsigned short*)(g_wpack + (size_t)mat * 16384);
    unsigned short* lo = (unsigned short*)(g_wpack + (size_t)mat * 16384 + 8192);
    int n  = threadIdx.x & 127;
    int kc = threadIdx.x >> 7;
#pragma unroll
    for (int j = 0; j < 16; j++) {
        int k = kc * 16 + j;
        float w = __ldg(&W[k * 128 + n]);
        __nv_bfloat16 h = __float2bfloat16(w);
        float l = w - __bfloat162float(h);
        hi[n * 128 + k] = __bfloat16_as_ushort(h);
        lo[n * 128 + k] = __bfloat16_as_ushort(__float2bfloat16(l));
    }
}

// ---------------- GEMM building blocks (256 threads/CTA, 128-row tiles) ----------------
static __device__ __forceinline__ void conv_A(char* sm, const float* __restrict__ A,
                                              int row0, int N) {
#pragma unroll
    for (int it = 0; it < 16; it++) {
        int idx = it * 256 + threadIdx.x;   // 0..4095
        int r  = idx >> 5;
        int c4 = idx & 31;
        int gidx = row0 + r;
        int gc = gidx < N ? gidx : N - 1;
        float4 v = __ldg(((const float4*)(A + (size_t)gc * 128)) + c4);
        float hx = bf16r(v.x), hy = bf16r(v.y), hz = bf16r(v.z), hw = bf16r(v.w);
        *(uint2*)(sm + AH_OFF + r * ROWB + c4 * 8) =
            make_uint2(pack_bf2(v.x, v.y), pack_bf2(v.z, v.w));
        *(uint2*)(sm + AL_OFF + r * ROWB + c4 * 8) =
            make_uint2(pack_bf2(v.x - hx, v.y - hy), pack_bf2(v.z - hz, v.w - hw));
    }
}

// async copy one weight image (hi+lo) into a B buffer; caller commits group
static __device__ __forceinline__ void copy_B_async(uint32_t sbase, int bufOff, int widx) {
    const char* src = (const char*)(g_wpack + (size_t)widx * 16384);
    uint32_t dst = sbase + bufOff;
#pragma unroll
    for (int it = 0; it < 8; it++) {
        int i = it * 256 + threadIdx.x;   // 0..2047
        int r = i >> 4, c = i & 15;
        cp16(dst + r * ROWB + c * 16,        src + i * 16);            // hi
        cp16(dst + T_SZ + r * ROWB + c * 16, src + 32768 + i * 16);    // lo
    }
    cp_commit();
}

static __device__ __forceinline__ void mma_bf16(float* c, const uint32_t* a,
                                                uint32_t b0, uint32_t b1) {
    asm volatile("mma.sync.aligned.m16n8k16.row.col.f32.bf16.bf16.f32 "
                 "{%0,%1,%2,%3}, {%4,%5,%6,%7}, {%8,%9}, {%0,%1,%2,%3};"
                 : "+f"(c[0]), "+f"(c[1]), "+f"(c[2]), "+f"(c[3])
                 : "r"(a[0]), "r"(a[1]), "r"(a[2]), "r"(a[3]), "r"(b0), "r"(b1));
}
static __device__ __forceinline__ void ldsm_x4(uint32_t* r, uint32_t addr) {
    asm volatile("ldmatrix.sync.aligned.m8n8.x4.shared.b16 {%0,%1,%2,%3}, [%4];"
                 : "=r"(r[0]), "=r"(r[1]), "=r"(r[2]), "=r"(r[3]) : "r"(addr));
}

// warp tile 32(M) x 64(N); the 3 split products (AH*BH + AL*BH + AH*BL)
// fused into ONE k-loop: each fragment loaded once per k-step.
static __device__ __forceinline__ void run_mma3(float acc[2][8][4], uint32_t sbase,
                                                int bufOff, int mbase, int nbase, int lane) {
    // A x4 address: lanes 0-15 rows, lanes16-31 +16B col (canonical m16k16)
    uint32_t aoff = (uint32_t)((mbase + (lane & 15)) * ROWB + (lane >> 4) * 16);
    // B x4 address: groups of 8 lanes -> (rows nf*8, kb) (rows nf*8, kb+16)
    //               (rows nf*8+8, kb) (rows nf*8+8, kb+16)
    uint32_t brow = (uint32_t)(nbase + (lane & 7) + ((lane >> 4) << 3));
    uint32_t boff = brow * ROWB + ((lane >> 3) & 1) * 16;
    uint32_t AH = sbase + AH_OFF + aoff;
    uint32_t AL = sbase + AL_OFF + aoff;
    uint32_t BH = sbase + bufOff + boff;
    uint32_t BL = BH + T_SZ;
#pragma unroll
    for (int ks = 0; ks < 8; ks++) {
        uint32_t kb = ks * 32;
        uint32_t ah0[4], ah1[4], al0[4], al1[4];
        ldsm_x4(ah0, AH + kb);
        ldsm_x4(ah1, AH + 16 * ROWB + kb);
        ldsm_x4(al0, AL + kb);
        ldsm_x4(al1, AL + 16 * ROWB + kb);
#pragma unroll
        for (int p = 0; p < 4; p++) {
            uint32_t bh[4], bl[4];
            ldsm_x4(bh, BH + p * (16 * ROWB) + kb);
            ldsm_x4(bl, BL + p * (16 * ROWB) + kb);
            int nf0 = 2 * p, nf1 = 2 * p + 1;
            // AH * BH
            mma_bf16(acc[0][nf0], ah0, bh[0], bh[1]);
            mma_bf16(acc[1][nf0], ah1, bh[0], bh[1]);
            mma_bf16(acc[0][nf1], ah0, bh[2], bh[3]);
            mma_bf16(acc[1][nf1], ah1, bh[2], bh[3]);
            // AL * BH
            mma_bf16(acc[0][nf0], al0, bh[0], bh[1]);
            mma_bf16(acc[1][nf0], al1, bh[0], bh[1]);
            mma_bf16(acc[0][nf1], al0, bh[2], bh[3]);
            mma_bf16(acc[1][nf1], al1, bh[2], bh[3]);
            // AH * BL
            mma_bf16(acc[0][nf0], ah0, bl[0], bl[1]);
            mma_bf16(acc[1][nf0], ah1, bl[0], bl[1]);
            mma_bf16(acc[0][nf1], ah0, bl[2], bl[3]);
            mma_bf16(acc[1][nf1], ah1, bl[2], bl[3]);
        }
    }
}

static __device__ __forceinline__ void zero_acc(float acc[2][8][4]) {
#pragma unroll
    for (int mf = 0; mf < 2; mf++)
#pragma unroll
        for (int nf = 0; nf < 8; nf++)
#pragma unroll
            for (int i = 0; i < 4; i++) acc[mf][nf][i] = 0.f;
}

// epilogue: write (doAdd=0) or accumulate (doAdd=1) to out
static __device__ __forceinline__ void epi(float acc[2][8][4], float* __restrict__ out,
                                           int row0, int mbase, int nbase, int g, int t,
                                           const float* b0, const float* b1, const float* b2,
                                           int N, int doAdd) {
    float bias[8][2];
#pragma unroll
    for (int nf = 0; nf < 8; nf++) {
#pragma unroll
        for (int i = 0; i < 2; i++) {
            float bb = 0.f;
            int col = nbase + nf * 8 + t * 2 + i;
            if (b0) bb += __ldg(&b0[col]);
            if (b1) bb += __ldg(&b1[col]);
            if (b2) bb += __ldg(&b2[col]);
            bias[nf][i] = bb;
        }
    }
#pragma unroll
    for (int mf = 0; mf < 2; mf++) {
#pragma unroll
        for (int half = 0; half < 2; half++) {
            int row = row0 + mbase + mf * 16 + g + half * 8;
            if (row < N) {
                float* op = out + (size_t)row * 128 + nbase;
#pragma unroll
                for (int nf = 0; nf < 8; nf++) {
                    float x = acc[mf][nf][half * 2 + 0] + bias[nf][0];
                    float y = acc[mf][nf][half * 2 + 1] + bias[nf][1];
                    float2* p = (float2*)(op + nf * 8 + t * 2);
                    if (doAdd) {
                        float2 o = *p;
                        o.x += x; o.y += y;
                        *p = o;
                    } else {
                        *p = make_float2(x, y);
                    }
                }
            }
        }
    }
}

// h = leaky(acc + br): store into A smem (hi/lo) and optionally gmem
static __device__ __forceinline__ void store_h(float acc[2][8][4], char* sm,
                                               const float* __restrict__ br_,
                                               float* __restrict__ hout,
                                               int row0, int mbase, int nbase,
                                               int g, int t, int N) {
    float bias[8][2];
#pragma unroll
    for (int nf = 0; nf < 8; nf++) {
#pragma unroll
        for (int i = 0; i < 2; i++)
            bias[nf][i] = __ldg(&br_[nbase + nf * 8 + t * 2 + i]);
    }
#pragma unroll
    for (int mf = 0; mf < 2; mf++) {
#pragma unroll
        for (int half = 0; half < 2; half++) {
            int rl = mbase + mf * 16 + g + half * 8;
            int row = row0 + rl;
#pragma unroll
            for (int nf = 0; nf < 8; nf++) {
                float x = leakyf(acc[mf][nf][half * 2 + 0] + bias[nf][0]);
                float y = leakyf(acc[mf][nf][half * 2 + 1] + bias[nf][1]);
                int c = nbase + nf * 8 + t * 2;
                float hx = bf16r(x), hy = bf16r(y);
                *(unsigned*)(sm + AH_OFF + rl * ROWB + c * 2) = pack_bf2(x, y);
                *(unsigned*)(sm + AL_OFF + rl * ROWB + c * 2) = pack_bf2(x - hx, y - hy);
                if (hout && row < N)
                    *(float2*)(hout + (size_t)row * 128 + c) = make_float2(x, y);
            }
        }
    }
}

// ---------------- kernel: hq = A@Wq+bq ; hk = A@Wk+bk ; [out = A@Wro+bro_sum] ----------------
__global__ void __launch_bounds__(256, 1)
gemm_qk3(const float* __restrict__ A, int wq, int wk, int wo,
         const float* __restrict__ bq, const float* __restrict__ bk,
         const float* __restrict__ bro,
         float* __restrict__ hq, float* __restrict__ hk, float* __restrict__ out, int N) {
    extern __shared__ char sm[];
    uint32_t sbase = smem_u32(sm);
    int tid = threadIdx.x, w = tid >> 5, lane = tid & 31;
    int g = lane >> 2, t = lane & 3;
    int mbase = (w >> 1) * 32, nbase = (w & 1) * 64;
    int row0 = blockIdx.x * 128;

    copy_B_async(sbase, B0_OFF, wq);      // group 1
    conv_A(sm, A, row0, N);
    copy_B_async(sbase, B1_OFF, wk);      // group 2

    cp_wait1();                            // buf0 ready
    __syncthreads();

    float acc[2][8][4];
    zero_acc(acc);
    run_mma3(acc, sbase, B0_OFF, mbase, nbase, lane);
    epi(acc, hq, row0, mbase, nbase, g, t, bq, nullptr, nullptr, N, 0);

    cp_wait0();                            // buf1 ready
    __syncthreads();                       // everyone done with buf0
    if (wo >= 0) copy_B_async(sbase, B0_OFF, wo);   // group 3 (into buf0)

    zero_acc(acc);
    run_mma3(acc, sbase, B1_OFF, mbase, nbase, lane);
    epi(acc, hk, row0, mbase, nbase, g, t, bk, nullptr, nullptr, N, 0);

    if (wo >= 0) {
        cp_wait0();
        __syncthreads();
        zero_acc(acc);
        run_mma3(acc, sbase, B0_OFF, mbase, nbase, lane);
        epi(acc, out, row0, mbase, nbase, g, t, bro, bro + 128, bro + 256, N, 0);
    }
}

// ---------------- kernel: h = leaky(agg@Wr+br) [-> hout]; out += h@Wro ----------------
__global__ void __launch_bounds__(256, 1)
gemm_wr_ro(const float* __restrict__ agg, int wr, int wro,
           const float* __restrict__ br_, float* __restrict__ hout,
           float* __restrict__ out, int N) {
    extern __shared__ char sm[];
    uint32_t sbase = smem_u32(sm);
    int tid = threadIdx.x, w = tid >> 5, lane = tid & 31;
    int g = lane >> 2, t = lane & 3;
    int mbase = (w >> 1) * 32, nbase = (w & 1) * 64;
    int row0 = blockIdx.x * 128;

    copy_B_async(sbase, B0_OFF, wr);      // group 1
    conv_A(sm, agg, row0, N);
    copy_B_async(sbase, B1_OFF, wro);     // group 2

    cp_wait1();
    __syncthreads();

    float acc[2][8][4];
    zero_acc(acc);
    run_mma3(acc, sbase, B0_OFF, mbase, nbase, lane);

    __syncthreads();                       // all warps done reading A
    store_h(acc, sm, br_, hout, row0, mbase, nbase, g, t, N);
    cp_wait0();                            // buf1 (Wro) ready
    __syncthreads();                       // h tiles visible to all

    zero_acc(acc);
    run_mma3(acc, sbase, B1_OFF, mbase, nbase, lane);
    epi(acc, out, row0, mbase, nbase, g, t, nullptr, nullptr, nullptr, N, 1);
}

// ---------------- launch ----------------
extern "C" void kernel_launch(void* const* d_in, const int* in_sizes, int n_in,
                              void* d_out, int out_size) {
    const float* feats = (const float*)d_in[0];
    const float* Wq    = (const float*)d_in[1];
    const float* bq    = (const float*)d_in[2];
    const float* Wk    = (const float*)d_in[3];
    const float* bk    = (const float*)d_in[4];
    const float* Wr    = (const float*)d_in[5];
    const float* br    = (const float*)d_in[6];
    const float* Wro   = (const float*)d_in[7];
    const float* bro   = (const float*)d_in[8];
    const int*   src   = (const int*)d_in[9];
    const int*   dst   = (const int*)d_in[10];

    int N = in_sizes[0] / DIM;   // 50000
    int E = in_sizes[9];         // 800000
    float* out = (float*)d_out;

    float *hq, *hk, *agg, *h1;
    int *cnt, *off, *cur, *csrc, *bsum;
    cudaGetSymbolAddress((void**)&hq,   g_hq);
    cudaGetSymbolAddress((void**)&hk,   g_hk);
    cudaGetSymbolAddress((void**)&agg,  g_agg);
    cudaGetSymbolAddress((void**)&h1,   g_h1);
    cudaGetSymbolAddress((void**)&cnt,  g_cnt);
    cudaGetSymbolAddress((void**)&off,  g_off);
    cudaGetSymbolAddress((void**)&cur,  g_cur);
    cudaGetSymbolAddress((void**)&csrc, g_csrc);
    cudaGetSymbolAddress((void**)&bsum, g_bsum);

    cudaFuncSetAttribute(gemm_qk3,   cudaFuncAttributeMaxDynamicSharedMemorySize, SMEM_TOTAL);
    cudaFuncSetAttribute(gemm_wr_ro, cudaFuncAttributeMaxDynamicSharedMemorySize, SMEM_TOTAL);

    int gM = (N + 127) / 128;    // 391
    int gAgg = (N * 32 + 255) / 256;
    int nb = (N + SCAN_BLK - 1) / SCAN_BLK;

    // weight packing
    pack_w<<<9, 1024>>>(Wq, Wk, Wr, Wro);

    // CSR build (by dst)
    zero_int<<<(N + 255) / 256, 256>>>(cnt, N);
    cnt_kernel<<<(E + 255) / 256, 256>>>(dst, E, cnt);
    scan_p1<<<nb, 256>>>(cnt, bsum, N);
    scan_p2<<<1, 32>>>(bsum, off, nb, N);
    scan_p3<<<nb, SCAN_BLK>>>(cnt, bsum, off, cur, N);
    scatter_kernel<<<(E + 255) / 256, 256>>>(src, dst, E, cur, csrc);

    // ---- layer 0 (+ readout stage 0 with all biases folded) ----
    gemm_qk3<<<gM, 256, SMEM_TOTAL>>>(feats, 0, 1, 6, bq, bk, bro, hq, hk, out, N);
    agg_csr<<<gAgg, 256>>>(off, csrc, hq, hk, agg, N);
    gemm_wr_ro<<<gM, 256, SMEM_TOTAL>>>(agg, 2, 7, br, h1, out, N);   // h1 + readout 1

    // ---- layer 1 (+ readout stage 2; h2 never hits gmem) ----
    gemm_qk3<<<gM, 256, SMEM_TOTAL>>>(h1, 3, 4, -1, bq + 128, bk + 128, nullptr,
                                      hq, hk, nullptr, N);
    agg_csr<<<gAgg, 256>>>(off, csrc, hq, hk, agg, N);
    gemm_wr_ro<<<gM, 256, SMEM_TOTAL>>>(agg, 5, 8, br + 128, nullptr, out, N);
}

// round 10
// speedup vs baseline: 1.1634x; 1.0440x over previous
#include <cuda_runtime.h>
#include <cuda_bf16.h>
#include <cstdint>
#include <cstddef>

// ---------------- problem constants ----------------
#define N_NODES 50000
#define N_EDGES 800000
#define DIM     128
#define NEG_SLOPE 0.2f

// ---- SMEM: A hi/lo (128 rows) + two B hi/lo buffers, 272B padded rows ----
#define ROWB      272
#define T_SZ      (128 * ROWB)          // 34816
#define AH_OFF    0
#define AL_OFF    T_SZ
#define B0_OFF    (2 * T_SZ)
#define B1_OFF    (4 * T_SZ)
#define SMEM_TOTAL (6 * T_SZ)           // 208896

#define SCAN_BLK 1024
#define MAX_SB   64

// ---------------- scratch (device globals; no allocs allowed) ----------------
__device__ float g_hq [(size_t)N_NODES * DIM];
__device__ float g_hk [(size_t)N_NODES * DIM];
__device__ float g_agg[(size_t)N_NODES * DIM];
__device__ float g_h1 [(size_t)N_NODES * DIM];
__device__ unsigned g_wpack[9 * 16384];
__device__ int g_cnt[N_NODES];
__device__ int g_off[N_NODES + 1];
__device__ int g_cur[N_NODES];
__device__ int g_csrc[N_EDGES];
__device__ int g_bsum[MAX_SB];

__device__ __forceinline__ float leakyf(float x) { return x >= 0.f ? x : NEG_SLOPE * x; }

static __device__ __forceinline__ unsigned pack_bf2(float a, float b) {
    __nv_bfloat162 h = __floats2bfloat162_rn(a, b);
    return *(unsigned*)&h;
}
static __device__ __forceinline__ float bf16r(float x) {
    return __bfloat162float(__float2bfloat16(x));
}
static __device__ __forceinline__ uint32_t smem_u32(const void* p) {
    uint32_t a;
    asm("{ .reg .u64 t; cvta.to.shared.u64 t, %1; cvt.u32.u64 %0, t; }" : "=r"(a) : "l"(p));
    return a;
}
static __device__ __forceinline__ void cp16(uint32_t d, const void* s) {
    asm volatile("cp.async.cg.shared.global [%0], [%1], 16;" :: "r"(d), "l"(s));
}
static __device__ __forceinline__ void cp_commit() {
    asm volatile("cp.async.commit_group;");
}
static __device__ __forceinline__ void cp_wait0() {
    asm volatile("cp.async.wait_group 0;");
}
static __device__ __forceinline__ void cp_wait1() {
    asm volatile("cp.async.wait_group 1;");
}

// ---------------- CSR build ----------------
__global__ void zero_int(int* __restrict__ p, int n) {
    int i = blockIdx.x * blockDim.x + threadIdx.x;
    if (i < n) p[i] = 0;
}
// 4 edges per thread, vectorized
__global__ void cnt_kernel(const int* __restrict__ dst, int E, int* __restrict__ cnt) {
    int i4 = blockIdx.x * blockDim.x + threadIdx.x;
    int base = i4 * 4;
    if (base + 3 < E) {
        int4 d = __ldg((const int4*)(dst + base));
        atomicAdd(&cnt[d.x], 1);
        atomicAdd(&cnt[d.y], 1);
        atomicAdd(&cnt[d.z], 1);
        atomicAdd(&cnt[d.w], 1);
    } else {
        for (int j = base; j < E; j++) atomicAdd(&cnt[__ldg(&dst[j])], 1);
    }
}
__global__ void scan_p1(const int* __restrict__ cnt, int* __restrict__ bsum, int n) {
    __shared__ int wsh[8];
    int tid = threadIdx.x;
    int base = blockIdx.x * SCAN_BLK;
    int s = 0;
#pragma unroll
    for (int j = 0; j < 4; j++) {
        int i = base + j * 256 + tid;
        if (i < n) s += __ldg(&cnt[i]);
    }
#pragma unroll
    for (int d = 16; d > 0; d >>= 1) s += __shfl_down_sync(0xffffffffu, s, d);
    if ((tid & 31) == 0) wsh[tid >> 5] = s;
    __syncthreads();
    if (tid < 8) {
        int v = wsh[tid];
#pragma unroll
        for (int d = 4; d > 0; d >>= 1) v += __shfl_down_sync(0xffu, v, d);
        if (tid == 0) bsum[blockIdx.x] = v;
    }
}
__global__ void scan_p2(int* __restrict__ bsum, int* __restrict__ off, int nb, int n) {
    int lane = threadIdx.x;
    int v0 = (lane < nb)      ? bsum[lane]      : 0;
    int v1 = (32 + lane < nb) ? bsum[32 + lane] : 0;
    int s0 = v0, s1 = v1;
#pragma unroll
    for (int d = 1; d < 32; d <<= 1) {
        int t0 = __shfl_up_sync(0xffffffffu, s0, d);
        int t1 = __shfl_up_sync(0xffffffffu, s1, d);
        if (lane >= d) { s0 += t0; s1 += t1; }
    }
    int tot0 = __shfl_sync(0xffffffffu, s0, 31);
    int tot1 = __shfl_sync(0xffffffffu, s1, 31);
    if (lane < nb)      bsum[lane]      = s0 - v0;
    if (32 + lane < nb) bsum[32 + lane] = tot0 + s1 - v1;
    if (lane == 0) off[n] = tot0 + tot1;
}
__global__ void scan_p3(const int* __restrict__ cnt, const int* __restrict__ bsum,
                        int* __restrict__ off, int* __restrict__ cur, int n) {
    __shared__ int wsh[32];
    int tid = threadIdx.x;
    int lane = tid & 31, w = tid >> 5;
    int i = blockIdx.x * SCAN_BLK + tid;
    int v = (i < n) ? __ldg(&cnt[i]) : 0;
    int s = v;
#pragma unroll
    for (int d = 1; d < 32; d <<= 1) {
        int t = __shfl_up_sync(0xffffffffu, s, d);
        if (lane >= d) s += t;
    }
    if (lane == 31) wsh[w] = s;
    __syncthreads();
    if (w == 0) {
        int x = wsh[lane];
#pragma unroll
        for (int d = 1; d < 32; d <<= 1) {
            int t = __shfl_up_sync(0xffffffffu, x, d);
            if (lane >= d) x += t;
        }
        wsh[lane] = x;
    }
    __syncthreads();
    int excl = s - v + (w ? wsh[w - 1] : 0) + __ldg(&bsum[blockIdx.x]);
    if (i < n) { off[i] = excl; cur[i] = excl; }
}
__global__ void scatter_kernel(const int* __restrict__ src, const int* __restrict__ dst,
                               int E, int* __restrict__ cur, int* __restrict__ csrc) {
    int i4 = blockIdx.x * blockDim.x + threadIdx.x;
    int base = i4 * 4;
    if (base + 3 < E) {
        int4 d = __ldg((const int4*)(dst + base));
        int4 s = __ldg((const int4*)(src + base));
        csrc[atomicAdd(&cur[d.x], 1)] = s.x;
        csrc[atomicAdd(&cur[d.y], 1)] = s.y;
        csrc[atomicAdd(&cur[d.z], 1)] = s.z;
        csrc[atomicAdd(&cur[d.w], 1)] = s.w;
    } else {
        for (int j = base; j < E; j++) {
            int pos = atomicAdd(&cur[__ldg(&dst[j])], 1);
            csrc[pos] = __ldg(&src[j]);
        }
    }
}

// ---------------- CSR aggregation: warp per dst node, no atomics ----------------
__global__ void agg_csr(const int* __restrict__ off, const int* __restrict__ csrc,
                        const float* __restrict__ hq, const float* __restrict__ hk,
                        float* __restrict__ agg, int N) {
    int warp = (blockIdx.x * blockDim.x + threadIdx.x) >> 5;
    int lane = threadIdx.x & 31;
    if (warp >= N) return;
    int b = __ldg(&off[warp]);
    int e = __ldg(&off[warp + 1]);
    float4 q = __ldg(((const float4*)hq) + (size_t)warp * 32 + lane);
    float4 acc = make_float4(0.f, 0.f, 0.f, 0.f);
    for (int base = b; base < e; base += 32) {
        int s = (base + lane < e) ? __ldg(&csrc[base + lane]) : 0;
        int m = min(32, e - base);
        for (int j = 0; j < m; j++) {
            int sj = __shfl_sync(0xffffffffu, s, j);
            float4 k = __ldg(((const float4*)hk) + (size_t)sj * 32 + lane);
            acc.x += leakyf(q.x + k.x);
            acc.y += leakyf(q.y + k.y);
            acc.z += leakyf(q.z + k.z);
            acc.w += leakyf(q.w + k.w);
        }
    }
    float inv = 1.f / (float)max(e - b, 1);
    ((float4*)agg)[(size_t)warp * 32 + lane] =
        make_float4(acc.x * inv, acc.y * inv, acc.z * inv, acc.w * inv);
}

// ---------------- pack weights: bf16 hi/lo images, layout [n][k] ----------------
__global__ void pack_w(const float* __restrict__ Wq, const float* __restrict__ Wk,
                       const float* __restrict__ Wr, const float* __restrict__ Wro) {
    int mat = blockIdx.x;  // 0..8
    const float* W;
    switch (mat) {
        case 0: W = Wq;         break;
        case 1: W = Wk;         break;
        case 2: W = Wr;         break;
        case 3: W = Wq + 16384; break;
        case 4: W = Wk + 16384; break;
        case 5: W = Wr + 16384; break;
        default: W = Wro + (mat - 6) * 16384; break;
    }
    unsigned short* hi = (unsigned short*)(g_wpack + (size_t)mat * 16384);
    unsigned short* lo = (unsigned short*)(g_wpack + (size_t)mat * 16384 + 8192);
    int n  = threadIdx.x & 127;
    int kc = threadIdx.x >> 7;
#pragma unroll
    for (int j = 0; j < 16; j++) {
        int k = kc * 16 + j;
        float w = __ldg(&W[k * 128 + n]);
        __nv_bfloat16 h = __float2bfloat16(w);
        float l = w - __bfloat162float(h);
        hi[n * 128 + k] = __bfloat16_as_ushort(h);
        lo[n * 128 + k] = __bfloat16_as_ushort(__float2bfloat16(l));
    }
}

// ---------------- GEMM building blocks (256 threads/CTA, 128-row tiles) ----------------
static __device__ __forceinline__ void conv_A(char* sm, const float* __restrict__ A,
                                              int row0, int N) {
#pragma unroll
    for (int it = 0; it < 16; it++) {
        int idx = it * 256 + threadIdx.x;
        int r  = idx >> 5;
        int c4 = idx & 31;
        int gidx = row0 + r;
        int gc = gidx < N ? gidx : N - 1;
        float4 v = __ldg(((const float4*)(A + (size_t)gc * 128)) + c4);
        float hx = bf16r(v.x), hy = bf16r(v.y), hz = bf16r(v.z), hw = bf16r(v.w);
        *(uint2*)(sm + AH_OFF + r * ROWB + c4 * 8) =
            make_uint2(pack_bf2(v.x, v.y), pack_bf2(v.z, v.w));
        *(uint2*)(sm + AL_OFF + r * ROWB + c4 * 8) =
            make_uint2(pack_bf2(v.x - hx, v.y - hy), pack_bf2(v.z - hz, v.w - hw));
    }
}

static __device__ __forceinline__ void copy_B_async(uint32_t sbase, int bufOff, int widx) {
    const char* src = (const char*)(g_wpack + (size_t)widx * 16384);
    uint32_t dst = sbase + bufOff;
#pragma unroll
    for (int it = 0; it < 8; it++) {
        int i = it * 256 + threadIdx.x;
        int r = i >> 4, c = i & 15;
        cp16(dst + r * ROWB + c * 16,        src + i * 16);
        cp16(dst + T_SZ + r * ROWB + c * 16, src + 32768 + i * 16);
    }
    cp_commit();
}

static __device__ __forceinline__ void mma_bf16(float* c, const uint32_t* a,
                                                uint32_t b0, uint32_t b1) {
    asm volatile("mma.sync.aligned.m16n8k16.row.col.f32.bf16.bf16.f32 "
                 "{%0,%1,%2,%3}, {%4,%5,%6,%7}, {%8,%9}, {%0,%1,%2,%3};"
                 : "+f"(c[0]), "+f"(c[1]), "+f"(c[2]), "+f"(c[3])
                 : "r"(a[0]), "r"(a[1]), "r"(a[2]), "r"(a[3]), "r"(b0), "r"(b1));
}
static __device__ __forceinline__ void ldsm_x4(uint32_t* r, uint32_t addr) {
    asm volatile("ldmatrix.sync.aligned.m8n8.x4.shared.b16 {%0,%1,%2,%3}, [%4];"
                 : "=r"(r[0]), "=r"(r[1]), "=r"(r[2]), "=r"(r[3]) : "r"(addr));
}

// warp tile 32(M) x 64(N); fused 3-term split (AH*BH + AL*BH + AH*BL)
static __device__ __forceinline__ void run_mma3(float acc[2][8][4], uint32_t sbase,
                                                int bufOff, int mbase, int nbase, int lane) {
    uint32_t aoff = (uint32_t)((mbase + (lane & 15)) * ROWB + (lane >> 4) * 16);
    uint32_t brow = (uint32_t)(nbase + (lane & 7) + ((lane >> 4) << 3));
    uint32_t boff = brow * ROWB + ((lane >> 3) & 1) * 16;
    uint32_t AH = sbase + AH_OFF + aoff;
    uint32_t AL = sbase + AL_OFF + aoff;
    uint32_t BH = sbase + bufOff + boff;
    uint32_t BL = BH + T_SZ;
#pragma unroll
    for (int ks = 0; ks < 8; ks++) {
        uint32_t kb = ks * 32;
        uint32_t ah0[4], ah1[4], al0[4], al1[4];
        ldsm_x4(ah0, AH + kb);
        ldsm_x4(ah1, AH + 16 * ROWB + kb);
        ldsm_x4(al0, AL + kb);
        ldsm_x4(al1, AL + 16 * ROWB + kb);
#pragma unroll
        for (int p = 0; p < 4; p++) {
            uint32_t bh[4], bl[4];
            ldsm_x4(bh, BH + p * (16 * ROWB) + kb);
            ldsm_x4(bl, BL + p * (16 * ROWB) + kb);
            int nf0 = 2 * p, nf1 = 2 * p + 1;
            mma_bf16(acc[0][nf0], ah0, bh[0], bh[1]);
            mma_bf16(acc[1][nf0], ah1, bh[0], bh[1]);
            mma_bf16(acc[0][nf1], ah0, bh[2], bh[3]);
            mma_bf16(acc[1][nf1], ah1, bh[2], bh[3]);
            mma_bf16(acc[0][nf0], al0, bh[0], bh[1]);
            mma_bf16(acc[1][nf0], al1, bh[0], bh[1]);
            mma_bf16(acc[0][nf1], al0, bh[2], bh[3]);
            mma_bf16(acc[1][nf1], al1, bh[2], bh[3]);
            mma_bf16(acc[0][nf0], ah0, bl[0], bl[1]);
            mma_bf16(acc[1][nf0], ah1, bl[0], bl[1]);
            mma_bf16(acc[0][nf1], ah0, bl[2], bl[3]);
            mma_bf16(acc[1][nf1], ah1, bl[2], bl[3]);
        }
    }
}

static __device__ __forceinline__ void zero_acc(float acc[2][8][4]) {
#pragma unroll
    for (int mf = 0; mf < 2; mf++)
#pragma unroll
        for (int nf = 0; nf < 8; nf++)
#pragma unroll
            for (int i = 0; i < 4; i++) acc[mf][nf][i] = 0.f;
}

static __device__ __forceinline__ void epi(float acc[2][8][4], float* __restrict__ out,
                                           int row0, int mbase, int nbase, int g, int t,
                                           const float* b0, const float* b1, const float* b2,
                                           int N, int doAdd) {
    float bias[8][2];
#pragma unroll
    for (int nf = 0; nf < 8; nf++) {
#pragma unroll
        for (int i = 0; i < 2; i++) {
            float bb = 0.f;
            int col = nbase + nf * 8 + t * 2 + i;
            if (b0) bb += __ldg(&b0[col]);
            if (b1) bb += __ldg(&b1[col]);
            if (b2) bb += __ldg(&b2[col]);
            bias[nf][i] = bb;
        }
    }
#pragma unroll
    for (int mf = 0; mf < 2; mf++) {
#pragma unroll
        for (int half = 0; half < 2; half++) {
            int row = row0 + mbase + mf * 16 + g + half * 8;
            if (row < N) {
                float* op = out + (size_t)row * 128 + nbase;
#pragma unroll
                for (int nf = 0; nf < 8; nf++) {
                    float x = acc[mf][nf][half * 2 + 0] + bias[nf][0];
                    float y = acc[mf][nf][half * 2 + 1] + bias[nf][1];
                    float2* p = (float2*)(op + nf * 8 + t * 2);
                    if (doAdd) {
                        float2 o = *p;
                        o.x += x; o.y += y;
                        *p = o;
                    } else {
                        *p = make_float2(x, y);
                    }
                }
            }
        }
    }
}

static __device__ __forceinline__ void store_h(float acc[2][8][4], char* sm,
                                               const float* __restrict__ br_,
                                               float* __restrict__ hout,
                                               int row0, int mbase, int nbase,
                                               int g, int t, int N) {
    float bias[8][2];
#pragma unroll
    for (int nf = 0; nf < 8; nf++) {
#pragma unroll
        for (int i = 0; i < 2; i++)
            bias[nf][i] = __ldg(&br_[nbase + nf * 8 + t * 2 + i]);
    }
#pragma unroll
    for (int mf = 0; mf < 2; mf++) {
#pragma unroll
        for (int half = 0; half < 2; half++) {
            int rl = mbase + mf * 16 + g + half * 8;
            int row = row0 + rl;
#pragma unroll
            for (int nf = 0; nf < 8; nf++) {
                float x = leakyf(acc[mf][nf][half * 2 + 0] + bias[nf][0]);
                float y = leakyf(acc[mf][nf][half * 2 + 1] + bias[nf][1]);
                int c = nbase + nf * 8 + t * 2;
                float hx = bf16r(x), hy = bf16r(y);
                *(unsigned*)(sm + AH_OFF + rl * ROWB + c * 2) = pack_bf2(x, y);
                *(unsigned*)(sm + AL_OFF + rl * ROWB + c * 2) = pack_bf2(x - hx, y - hy);
                if (hout && row < N)
                    *(float2*)(hout + (size_t)row * 128 + c) = make_float2(x, y);
            }
        }
    }
}

// ---------------- kernel: hq = A@Wq+bq ; hk = A@Wk+bk ; [out = A@Wro+bro_sum] ----------------
__global__ void __launch_bounds__(256, 1)
gemm_qk3(const float* __restrict__ A, int wq, int wk, int wo,
         const float* __restrict__ bq, const float* __restrict__ bk,
         const float* __restrict__ bro,
         float* __restrict__ hq, float* __restrict__ hk, float* __restrict__ out, int N) {
    extern __shared__ char sm[];
    uint32_t sbase = smem_u32(sm);
    int tid = threadIdx.x, w = tid >> 5, lane = tid & 31;
    int g = lane >> 2, t = lane & 3;
    int mbase = (w >> 1) * 32, nbase = (w & 1) * 64;
    int row0 = blockIdx.x * 128;

    copy_B_async(sbase, B0_OFF, wq);
    conv_A(sm, A, row0, N);
    copy_B_async(sbase, B1_OFF, wk);

    cp_wait1();
    __syncthreads();

    float acc[2][8][4];
    zero_acc(acc);
    run_mma3(acc, sbase, B0_OFF, mbase, nbase, lane);
    epi(acc, hq, row0, mbase, nbase, g, t, bq, nullptr, nullptr, N, 0);

    cp_wait0();
    __syncthreads();
    if (wo >= 0) copy_B_async(sbase, B0_OFF, wo);

    zero_acc(acc);
    run_mma3(acc, sbase, B1_OFF, mbase, nbase, lane);
    epi(acc, hk, row0, mbase, nbase, g, t, bk, nullptr, nullptr, N, 0);

    if (wo >= 0) {
        cp_wait0();
        __syncthreads();
        zero_acc(acc);
        run_mma3(acc, sbase, B0_OFF, mbase, nbase, lane);
        epi(acc, out, row0, mbase, nbase, g, t, bro, bro + 128, bro + 256, N, 0);
    }
}

// ---------------- kernel: h = leaky(agg@Wr+br) [-> hout]; out += h@Wro ----------------
__global__ void __launch_bounds__(256, 1)
gemm_wr_ro(const float* __restrict__ agg, int wr, int wro,
           const float* __restrict__ br_, float* __restrict__ hout,
           float* __restrict__ out, int N) {
    extern __shared__ char sm[];
    uint32_t sbase = smem_u32(sm);
    int tid = threadIdx.x, w = tid >> 5, lane = tid & 31;
    int g = lane >> 2, t = lane & 3;
    int mbase = (w >> 1) * 32, nbase = (w & 1) * 64;
    int row0 = blockIdx.x * 128;

    copy_B_async(sbase, B0_OFF, wr);
    conv_A(sm, agg, row0, N);
    copy_B_async(sbase, B1_OFF, wro);

    cp_wait1();
    __syncthreads();

    float acc[2][8][4];
    zero_acc(acc);
    run_mma3(acc, sbase, B0_OFF, mbase, nbase, lane);

    __syncthreads();
    store_h(acc, sm, br_, hout, row0, mbase, nbase, g, t, N);
    cp_wait0();
    __syncthreads();

    zero_acc(acc);
    run_mma3(acc, sbase, B1_OFF, mbase, nbase, lane);
    epi(acc, out, row0, mbase, nbase, g, t, nullptr, nullptr, nullptr, N, 1);
}

// ---------------- launch ----------------
extern "C" void kernel_launch(void* const* d_in, const int* in_sizes, int n_in,
                              void* d_out, int out_size) {
    const float* feats = (const float*)d_in[0];
    const float* Wq    = (const float*)d_in[1];
    const float* bq    = (const float*)d_in[2];
    const float* Wk    = (const float*)d_in[3];
    const float* bk    = (const float*)d_in[4];
    const float* Wr    = (const float*)d_in[5];
    const float* br    = (const float*)d_in[6];
    const float* Wro   = (const float*)d_in[7];
    const float* bro   = (const float*)d_in[8];
    const int*   src   = (const int*)d_in[9];
    const int*   dst   = (const int*)d_in[10];

    int N = in_sizes[0] / DIM;   // 50000
    int E = in_sizes[9];         // 800000
    float* out = (float*)d_out;

    float *hq, *hk, *agg, *h1;
    int *cnt, *off, *cur, *csrc, *bsum;
    cudaGetSymbolAddress((void**)&hq,   g_hq);
    cudaGetSymbolAddress((void**)&hk,   g_hk);
    cudaGetSymbolAddress((void**)&agg,  g_agg);
    cudaGetSymbolAddress((void**)&h1,   g_h1);
    cudaGetSymbolAddress((void**)&cnt,  g_cnt);
    cudaGetSymbolAddress((void**)&off,  g_off);
    cudaGetSymbolAddress((void**)&cur,  g_cur);
    cudaGetSymbolAddress((void**)&csrc, g_csrc);
    cudaGetSymbolAddress((void**)&bsum, g_bsum);

    cudaFuncSetAttribute(gemm_qk3,   cudaFuncAttributeMaxDynamicSharedMemorySize, SMEM_TOTAL);
    cudaFuncSetAttribute(gemm_wr_ro, cudaFuncAttributeMaxDynamicSharedMemorySize, SMEM_TOTAL);

    int gM = (N + 127) / 128;    // 391
    int gAgg = (N * 32 + 255) / 256;
    int nb = (N + SCAN_BLK - 1) / SCAN_BLK;
    int e4 = (E + 3) / 4;

    // fork a second stream for the CSR build (independent of weights/GEMM-L0)
    cudaStream_t s2;
    cudaStreamCreateWithFlags(&s2, cudaStreamNonBlocking);
    cudaEvent_t evF, evJ;
    cudaEventCreateWithFlags(&evF, cudaEventDisableTiming);
    cudaEventCreateWithFlags(&evJ, cudaEventDisableTiming);

    cudaEventRecord(evF, 0);
    cudaStreamWaitEvent(s2, evF, 0);

    // ---- branch A (s2): CSR build ----
    zero_int<<<(N + 255) / 256, 256, 0, s2>>>(cnt, N);
    cnt_kernel<<<(e4 + 255) / 256, 256, 0, s2>>>(dst, E, cnt);
    scan_p1<<<nb, 256, 0, s2>>>(cnt, bsum, N);
    scan_p2<<<1, 32, 0, s2>>>(bsum, off, nb, N);
    scan_p3<<<nb, SCAN_BLK, 0, s2>>>(cnt, bsum, off, cur, N);
    scatter_kernel<<<(e4 + 255) / 256, 256, 0, s2>>>(src, dst, E, cur, csrc);
    cudaEventRecord(evJ, s2);

    // ---- branch B (stream 0): weights + layer-0 Q/K/readout0 GEMM ----
    pack_w<<<9, 1024>>>(Wq, Wk, Wr, Wro);
    gemm_qk3<<<gM, 256, SMEM_TOTAL>>>(feats, 0, 1, 6, bq, bk, bro, hq, hk, out, N);

    // join: agg needs both branches
    cudaStreamWaitEvent(0, evJ, 0);

    agg_csr<<<gAgg, 256>>>(off, csrc, hq, hk, agg, N);
    gemm_wr_ro<<<gM, 256, SMEM_TOTAL>>>(agg, 2, 7, br, h1, out, N);

    gemm_qk3<<<gM, 256, SMEM_TOTAL>>>(h1, 3, 4, -1, bq + 128, bk + 128, nullptr,
                                      hq, hk, nullptr, N);
    agg_csr<<<gAgg, 256>>>(off, csrc, hq, hk, agg, N);
    gemm_wr_ro<<<gM, 256, SMEM_TOTAL>>>(agg, 5, 8, br + 128, nullptr, out, N);

    // NOTE: s2/evF/evJ intentionally not destroyed here — destroying a stream
    // that participated in an active capture is hazardous; kernel_launch is
    // invoked only a handful of times (host-side objects only, no device mem).
}

// round 11
// speedup vs baseline: 1.2412x; 1.0669x over previous
#include <cuda_runtime.h>
#include <cuda_bf16.h>
#include <cuda_fp16.h>
#include <cstdint>
#include <cstddef>

// ---------------- problem constants ----------------
#define N_NODES 50000
#define N_EDGES 800000
#define DIM     128
#define NEG_SLOPE 0.2f

// ---- SMEM: A hi/lo (128 rows) + two B hi/lo buffers, 272B padded rows ----
#define ROWB      272
#define T_SZ      (128 * ROWB)          // 34816
#define AH_OFF    0
#define AL_OFF    T_SZ
#define B0_OFF    (2 * T_SZ)
#define B1_OFF    (4 * T_SZ)
#define SMEM_TOTAL (6 * T_SZ)           // 208896

#define SCAN_BLK 1024
#define MAX_SB   64

// ---------------- scratch (device globals; no allocs allowed) ----------------
__device__ __half g_hq [(size_t)N_NODES * DIM];   // fp16 activation tables
__device__ __half g_hk [(size_t)N_NODES * DIM];
__device__ float  g_agg[(size_t)N_NODES * DIM];
__device__ float  g_h1 [(size_t)N_NODES * DIM];
__device__ unsigned g_wpack[9 * 16384];
__device__ int g_cnt[N_NODES];
__device__ int g_off[N_NODES + 1];
__device__ int g_cur[N_NODES];
__device__ int g_csrc[N_EDGES];
__device__ int g_bsum[MAX_SB];

__device__ __forceinline__ float leakyf(float x) { return x >= 0.f ? x : NEG_SLOPE * x; }

static __device__ __forceinline__ unsigned pack_bf2(float a, float b) {
    __nv_bfloat162 h = __floats2bfloat162_rn(a, b);
    return *(unsigned*)&h;
}
static __device__ __forceinline__ float bf16r(float x) {
    return __bfloat162float(__float2bfloat16(x));
}
static __device__ __forceinline__ uint32_t smem_u32(const void* p) {
    uint32_t a;
    asm("{ .reg .u64 t; cvta.to.shared.u64 t, %1; cvt.u32.u64 %0, t; }" : "=r"(a) : "l"(p));
    return a;
}
static __device__ __forceinline__ void cp16(uint32_t d, const void* s) {
    asm volatile("cp.async.cg.shared.global [%0], [%1], 16;" :: "r"(d), "l"(s));
}
static __device__ __forceinline__ void cp_commit() {
    asm volatile("cp.async.commit_group;");
}
static __device__ __forceinline__ void cp_wait0() {
    asm volatile("cp.async.wait_group 0;");
}
static __device__ __forceinline__ void cp_wait1() {
    asm volatile("cp.async.wait_group 1;");
}

// ---------------- CSR build ----------------
__global__ void zero_int(int* __restrict__ p, int n) {
    int i = blockIdx.x * blockDim.x + threadIdx.x;
    if (i < n) p[i] = 0;
}
__global__ void cnt_kernel(const int* __restrict__ dst, int E, int* __restrict__ cnt) {
    int i4 = blockIdx.x * blockDim.x + threadIdx.x;
    int base = i4 * 4;
    if (base + 3 < E) {
        int4 d = __ldg((const int4*)(dst + base));
        atomicAdd(&cnt[d.x], 1);
        atomicAdd(&cnt[d.y], 1);
        atomicAdd(&cnt[d.z], 1);
        atomicAdd(&cnt[d.w], 1);
    } else {
        for (int j = base; j < E; j++) atomicAdd(&cnt[__ldg(&dst[j])], 1);
    }
}
__global__ void scan_p1(const int* __restrict__ cnt, int* __restrict__ bsum, int n) {
    __shared__ int wsh[8];
    int tid = threadIdx.x;
    int base = blockIdx.x * SCAN_BLK;
    int s = 0;
#pragma unroll
    for (int j = 0; j < 4; j++) {
        int i = base + j * 256 + tid;
        if (i < n) s += __ldg(&cnt[i]);
    }
#pragma unroll
    for (int d = 16; d > 0; d >>= 1) s += __shfl_down_sync(0xffffffffu, s, d);
    if ((tid & 31) == 0) wsh[tid >> 5] = s;
    __syncthreads();
    if (tid < 8) {
        int v = wsh[tid];
#pragma unroll
        for (int d = 4; d > 0; d >>= 1) v += __shfl_down_sync(0xffu, v, d);
        if (tid == 0) bsum[blockIdx.x] = v;
    }
}
__global__ void scan_p2(int* __restrict__ bsum, int* __restrict__ off, int nb, int n) {
    int lane = threadIdx.x;
    int v0 = (lane < nb)      ? bsum[lane]      : 0;
    int v1 = (32 + lane < nb) ? bsum[32 + lane] : 0;
    int s0 = v0, s1 = v1;
#pragma unroll
    for (int d = 1; d < 32; d <<= 1) {
        int t0 = __shfl_up_sync(0xffffffffu, s0, d);
        int t1 = __shfl_up_sync(0xffffffffu, s1, d);
        if (lane >= d) { s0 += t0; s1 += t1; }
    }
    int tot0 = __shfl_sync(0xffffffffu, s0, 31);
    int tot1 = __shfl_sync(0xffffffffu, s1, 31);
    if (lane < nb)      bsum[lane]      = s0 - v0;
    if (32 + lane < nb) bsum[32 + lane] = tot0 + s1 - v1;
    if (lane == 0) off[n] = tot0 + tot1;
}
__global__ void scan_p3(const int* __restrict__ cnt, const int* __restrict__ bsum,
                        int* __restrict__ off, int* __restrict__ cur, int n) {
    __shared__ int wsh[32];
    int tid = threadIdx.x;
    int lane = tid & 31, w = tid >> 5;
    int i = blockIdx.x * SCAN_BLK + tid;
    int v = (i < n) ? __ldg(&cnt[i]) : 0;
    int s = v;
#pragma unroll
    for (int d = 1; d < 32; d <<= 1) {
        int t = __shfl_up_sync(0xffffffffu, s, d);
        if (lane >= d) s += t;
    }
    if (lane == 31) wsh[w] = s;
    __syncthreads();
    if (w == 0) {
        int x = wsh[lane];
#pragma unroll
        for (int d = 1; d < 32; d <<= 1) {
            int t = __shfl_up_sync(0xffffffffu, x, d);
            if (lane >= d) x += t;
        }
        wsh[lane] = x;
    }
    __syncthreads();
    int excl = s - v + (w ? wsh[w - 1] : 0) + __ldg(&bsum[blockIdx.x]);
    if (i < n) { off[i] = excl; cur[i] = excl; }
}
__global__ void scatter_kernel(const int* __restrict__ src, const int* __restrict__ dst,
                               int E, int* __restrict__ cur, int* __restrict__ csrc) {
    int i4 = blockIdx.x * blockDim.x + threadIdx.x;
    int base = i4 * 4;
    if (base + 3 < E) {
        int4 d = __ldg((const int4*)(dst + base));
        int4 s = __ldg((const int4*)(src + base));
        csrc[atomicAdd(&cur[d.x], 1)] = s.x;
        csrc[atomicAdd(&cur[d.y], 1)] = s.y;
        csrc[atomicAdd(&cur[d.z], 1)] = s.z;
        csrc[atomicAdd(&cur[d.w], 1)] = s.w;
    } else {
        for (int j = base; j < E; j++) {
            int pos = atomicAdd(&cur[__ldg(&dst[j])], 1);
            csrc[pos] = __ldg(&src[j]);
        }
    }
}

// ---------------- CSR aggregation: warp per dst node, fp16 tables ----------------
__global__ void agg_csr(const int* __restrict__ off, const int* __restrict__ csrc,
                        const __half* __restrict__ hq, const __half* __restrict__ hk,
                        float* __restrict__ agg, int N) {
    int warp = (blockIdx.x * blockDim.x + threadIdx.x) >> 5;
    int lane = threadIdx.x & 31;
    if (warp >= N) return;
    int b = __ldg(&off[warp]);
    int e = __ldg(&off[warp + 1]);
    // q: 4 halves per lane (8 bytes)
    uint2 qraw = __ldg(((const uint2*)hq) + (size_t)warp * 32 + lane);
    float2 q01 = __half22float2(*(const __half2*)&qraw.x);
    float2 q23 = __half22float2(*(const __half2*)&qraw.y);
    float4 q = make_float4(q01.x, q01.y, q23.x, q23.y);
    float4 acc = make_float4(0.f, 0.f, 0.f, 0.f);
    for (int base = b; base < e; base += 32) {
        int s = (base + lane < e) ? __ldg(&csrc[base + lane]) : 0;
        int m = min(32, e - base);
        for (int j = 0; j < m; j++) {
            int sj = __shfl_sync(0xffffffffu, s, j);
            uint2 kraw = __ldg(((const uint2*)hk) + (size_t)sj * 32 + lane);
            float2 k01 = __half22float2(*(const __half2*)&kraw.x);
            float2 k23 = __half22float2(*(const __half2*)&kraw.y);
            acc.x += leakyf(q.x + k01.x);
            acc.y += leakyf(q.y + k01.y);
            acc.z += leakyf(q.z + k23.x);
            acc.w += leakyf(q.w + k23.y);
        }
    }
    float inv = 1.f / (float)max(e - b, 1);
    ((float4*)agg)[(size_t)warp * 32 + lane] =
        make_float4(acc.x * inv, acc.y * inv, acc.z * inv, acc.w * inv);
}

// ---------------- pack weights: bf16 hi/lo images, layout [n][k] ----------------
__global__ void pack_w(const float* __restrict__ Wq, const float* __restrict__ Wk,
                       const float* __restrict__ Wr, const float* __restrict__ Wro) {
    int mat = blockIdx.x;  // 0..8
    const float* W;
    switch (mat) {
        case 0: W = Wq;         break;
        case 1: W = Wk;         break;
        case 2: W = Wr;         break;
        case 3: W = Wq + 16384; break;
        case 4: W = Wk + 16384; break;
        case 5: W = Wr + 16384; break;
        default: W = Wro + (mat - 6) * 16384; break;
    }
    unsigned short* hi = (unsigned short*)(g_wpack + (size_t)mat * 16384);
    unsigned short* lo = (unsigned short*)(g_wpack + (size_t)mat * 16384 + 8192);
    int n  = threadIdx.x & 127;
    int kc = threadIdx.x >> 7;
#pragma unroll
    for (int j = 0; j < 16; j++) {
        int k = kc * 16 + j;
        float w = __ldg(&W[k * 128 + n]);
        __nv_bfloat16 h = __float2bfloat16(w);
        float l = w - __bfloat162float(h);
        hi[n * 128 + k] = __bfloat16_as_ushort(h);
        lo[n * 128 + k] = __bfloat16_as_ushort(__float2bfloat16(l));
    }
}

// ---------------- GEMM building blocks (256 threads/CTA, 128-row tiles) ----------------
static __device__ __forceinline__ void conv_A(char* sm, const float* __restrict__ A,
                                              int row0, int N) {
#pragma unroll
    for (int it = 0; it < 16; it++) {
        int idx = it * 256 + threadIdx.x;
        int r  = idx >> 5;
        int c4 = idx & 31;
        int gidx = row0 + r;
        int gc = gidx < N ? gidx : N - 1;
        float4 v = __ldg(((const float4*)(A + (size_t)gc * 128)) + c4);
        float hx = bf16r(v.x), hy = bf16r(v.y), hz = bf16r(v.z), hw = bf16r(v.w);
        *(uint2*)(sm + AH_OFF + r * ROWB + c4 * 8) =
            make_uint2(pack_bf2(v.x, v.y), pack_bf2(v.z, v.w));
        *(uint2*)(sm + AL_OFF + r * ROWB + c4 * 8) =
            make_uint2(pack_bf2(v.x - hx, v.y - hy), pack_bf2(v.z - hz, v.w - hw));
    }
}

static __device__ __forceinline__ void copy_B_async(uint32_t sbase, int bufOff, int widx) {
    const char* src = (const char*)(g_wpack + (size_t)widx * 16384);
    uint32_t dst = sbase + bufOff;
#pragma unroll
    for (int it = 0; it < 8; it++) {
        int i = it * 256 + threadIdx.x;
        int r = i >> 4, c = i & 15;
        cp16(dst + r * ROWB + c * 16,        src + i * 16);
        cp16(dst + T_SZ + r * ROWB + c * 16, src + 32768 + i * 16);
    }
    cp_commit();
}

static __device__ __forceinline__ void mma_bf16(float* c, const uint32_t* a,
                                                uint32_t b0, uint32_t b1) {
    asm volatile("mma.sync.aligned.m16n8k16.row.col.f32.bf16.bf16.f32 "
                 "{%0,%1,%2,%3}, {%4,%5,%6,%7}, {%8,%9}, {%0,%1,%2,%3};"
                 : "+f"(c[0]), "+f"(c[1]), "+f"(c[2]), "+f"(c[3])
                 : "r"(a[0]), "r"(a[1]), "r"(a[2]), "r"(a[3]), "r"(b0), "r"(b1));
}
static __device__ __forceinline__ void ldsm_x4(uint32_t* r, uint32_t addr) {
    asm volatile("ldmatrix.sync.aligned.m8n8.x4.shared.b16 {%0,%1,%2,%3}, [%4];"
                 : "=r"(r[0]), "=r"(r[1]), "=r"(r[2]), "=r"(r[3]) : "r"(addr));
}

// warp tile 32(M) x 64(N); fused 3-term split (AH*BH + AL*BH + AH*BL)
static __device__ __forceinline__ void run_mma3(float acc[2][8][4], uint32_t sbase,
                                                int bufOff, int mbase, int nbase, int lane) {
    uint32_t aoff = (uint32_t)((mbase + (lane & 15)) * ROWB + (lane >> 4) * 16);
    uint32_t brow = (uint32_t)(nbase + (lane & 7) + ((lane >> 4) << 3));
    uint32_t boff = brow * ROWB + ((lane >> 3) & 1) * 16;
    uint32_t AH = sbase + AH_OFF + aoff;
    uint32_t AL = sbase + AL_OFF + aoff;
    uint32_t BH = sbase + bufOff + boff;
    uint32_t BL = BH + T_SZ;
#pragma unroll
    for (int ks = 0; ks < 8; ks++) {
        uint32_t kb = ks * 32;
        uint32_t ah0[4], ah1[4], al0[4], al1[4];
        ldsm_x4(ah0, AH + kb);
        ldsm_x4(ah1, AH + 16 * ROWB + kb);
        ldsm_x4(al0, AL + kb);
        ldsm_x4(al1, AL + 16 * ROWB + kb);
#pragma unroll
        for (int p = 0; p < 4; p++) {
            uint32_t bh[4], bl[4];
            ldsm_x4(bh, BH + p * (16 * ROWB) + kb);
            ldsm_x4(bl, BL + p * (16 * ROWB) + kb);
            int nf0 = 2 * p, nf1 = 2 * p + 1;
            mma_bf16(acc[0][nf0], ah0, bh[0], bh[1]);
            mma_bf16(acc[1][nf0], ah1, bh[0], bh[1]);
            mma_bf16(acc[0][nf1], ah0, bh[2], bh[3]);
            mma_bf16(acc[1][nf1], ah1, bh[2], bh[3]);
            mma_bf16(acc[0][nf0], al0, bh[0], bh[1]);
            mma_bf16(acc[1][nf0], al1, bh[0], bh[1]);
            mma_bf16(acc[0][nf1], al0, bh[2], bh[3]);
            mma_bf16(acc[1][nf1], al1, bh[2], bh[3]);
            mma_bf16(acc[0][nf0], ah0, bl[0], bl[1]);
            mma_bf16(acc[1][nf0], ah1, bl[0], bl[1]);
            mma_bf16(acc[0][nf1], ah0, bl[2], bl[3]);
            mma_bf16(acc[1][nf1], ah1, bl[2], bl[3]);
        }
    }
}

static __device__ __forceinline__ void zero_acc(float acc[2][8][4]) {
#pragma unroll
    for (int mf = 0; mf < 2; mf++)
#pragma unroll
        for (int nf = 0; nf < 8; nf++)
#pragma unroll
            for (int i = 0; i < 4; i++) acc[mf][nf][i] = 0.f;
}

// fp32 epilogue: write (doAdd=0) or accumulate (doAdd=1)
static __device__ __forceinline__ void epi(float acc[2][8][4], float* __restrict__ out,
                                           int row0, int mbase, int nbase, int g, int t,
                                           const float* b0, const float* b1, const float* b2,
                                           int N, int doAdd) {
    float bias[8][2];
#pragma unroll
    for (int nf = 0; nf < 8; nf++) {
#pragma unroll
        for (int i = 0; i < 2; i++) {
            float bb = 0.f;
            int col = nbase + nf * 8 + t * 2 + i;
            if (b0) bb += __ldg(&b0[col]);
            if (b1) bb += __ldg(&b1[col]);
            if (b2) bb += __ldg(&b2[col]);
            bias[nf][i] = bb;
        }
    }
#pragma unroll
    for (int mf = 0; mf < 2; mf++) {
#pragma unroll
        for (int half = 0; half < 2; half++) {
            int row = row0 + mbase + mf * 16 + g + half * 8;
            if (row < N) {
                float* op = out + (size_t)row * 128 + nbase;
#pragma unroll
                for (int nf = 0; nf < 8; nf++) {
                    float x = acc[mf][nf][half * 2 + 0] + bias[nf][0];
                    float y = acc[mf][nf][half * 2 + 1] + bias[nf][1];
                    float2* p = (float2*)(op + nf * 8 + t * 2);
                    if (doAdd) {
                        float2 o = *p;
                        o.x += x; o.y += y;
                        *p = o;
                    } else {
                        *p = make_float2(x, y);
                    }
                }
            }
        }
    }
}

// fp16 epilogue: out[row][col] = half(acc + bias)
static __device__ __forceinline__ void epi_h16(float acc[2][8][4], __half* __restrict__ out,
                                               int row0, int mbase, int nbase, int g, int t,
                                               const float* b0, int N) {
    float bias[8][2];
#pragma unroll
    for (int nf = 0; nf < 8; nf++) {
#pragma unroll
        for (int i = 0; i < 2; i++)
            bias[nf][i] = __ldg(&b0[nbase + nf * 8 + t * 2 + i]);
    }
#pragma unroll
    for (int mf = 0; mf < 2; mf++) {
#pragma unroll
        for (int half = 0; half < 2; half++) {
            int row = row0 + mbase + mf * 16 + g + half * 8;
            if (row < N) {
                __half* op = out + (size_t)row * 128 + nbase;
#pragma unroll
                for (int nf = 0; nf < 8; nf++) {
                    float x = acc[mf][nf][half * 2 + 0] + bias[nf][0];
                    float y = acc[mf][nf][half * 2 + 1] + bias[nf][1];
                    __half2 hv = __floats2half2_rn(x, y);
                    *(__half2*)(op + nf * 8 + t * 2) = hv;
                }
            }
        }
    }
}

// h = leaky(acc + br): store into A smem (hi/lo) and optionally gmem (fp32)
static __device__ __forceinline__ void store_h(float acc[2][8][4], char* sm,
                                               const float* __restrict__ br_,
                                               float* __restrict__ hout,
                                               int row0, int mbase, int nbase,
                                               int g, int t, int N) {
    float bias[8][2];
#pragma unroll
    for (int nf = 0; nf < 8; nf++) {
#pragma unroll
        for (int i = 0; i < 2; i++)
            bias[nf][i] = __ldg(&br_[nbase + nf * 8 + t * 2 + i]);
    }
#pragma unroll
    for (int mf = 0; mf < 2; mf++) {
#pragma unroll
        for (int half = 0; half < 2; half++) {
            int rl = mbase + mf * 16 + g + half * 8;
            int row = row0 + rl;
#pragma unroll
            for (int nf = 0; nf < 8; nf++) {
                float x = leakyf(acc[mf][nf][half * 2 + 0] + bias[nf][0]);
                float y = leakyf(acc[mf][nf][half * 2 + 1] + bias[nf][1]);
                int c = nbase + nf * 8 + t * 2;
                float hx = bf16r(x), hy = bf16r(y);
                *(unsigned*)(sm + AH_OFF + rl * ROWB + c * 2) = pack_bf2(x, y);
                *(unsigned*)(sm + AL_OFF + rl * ROWB + c * 2) = pack_bf2(x - hx, y - hy);
                if (hout && row < N)
                    *(float2*)(hout + (size_t)row * 128 + c) = make_float2(x, y);
            }
        }
    }
}

// ---------------- kernel: hq = A@Wq+bq ; hk = A@Wk+bk ; [out = A@Wro+bro_sum] ----------------
__global__ void __launch_bounds__(256, 1)
gemm_qk3(const float* __restrict__ A, int wq, int wk, int wo,
         const float* __restrict__ bq, const float* __restrict__ bk,
         const float* __restrict__ bro,
         __half* __restrict__ hq, __half* __restrict__ hk, float* __restrict__ out, int N) {
    extern __shared__ char sm[];
    uint32_t sbase = smem_u32(sm);
    int tid = threadIdx.x, w = tid >> 5, lane = tid & 31;
    int g = lane >> 2, t = lane & 3;
    int mbase = (w >> 1) * 32, nbase = (w & 1) * 64;
    int row0 = blockIdx.x * 128;

    copy_B_async(sbase, B0_OFF, wq);
    conv_A(sm, A, row0, N);
    copy_B_async(sbase, B1_OFF, wk);

    cp_wait1();
    __syncthreads();

    float acc[2][8][4];
    zero_acc(acc);
    run_mma3(acc, sbase, B0_OFF, mbase, nbase, lane);
    epi_h16(acc, hq, row0, mbase, nbase, g, t, bq, N);

    cp_wait0();
    __syncthreads();
    if (wo >= 0) copy_B_async(sbase, B0_OFF, wo);

    zero_acc(acc);
    run_mma3(acc, sbase, B1_OFF, mbase, nbase, lane);
    epi_h16(acc, hk, row0, mbase, nbase, g, t, bk, N);

    if (wo >= 0) {
        cp_wait0();
        __syncthreads();
        zero_acc(acc);
        run_mma3(acc, sbase, B0_OFF, mbase, nbase, lane);
        epi(acc, out, row0, mbase, nbase, g, t, bro, bro + 128, bro + 256, N, 0);
    }
}

// ---------------- kernel: h = leaky(agg@Wr+br) [-> hout]; out += h@Wro ----------------
__global__ void __launch_bounds__(256, 1)
gemm_wr_ro(const float* __restrict__ agg, int wr, int wro,
           const float* __restrict__ br_, float* __restrict__ hout,
           float* __restrict__ out, int N) {
    extern __shared__ char sm[];
    uint32_t sbase = smem_u32(sm);
    int tid = threadIdx.x, w = tid >> 5, lane = tid & 31;
    int g = lane >> 2, t = lane & 3;
    int mbase = (w >> 1) * 32, nbase = (w & 1) * 64;
    int row0 = blockIdx.x * 128;

    copy_B_async(sbase, B0_OFF, wr);
    conv_A(sm, agg, row0, N);
    copy_B_async(sbase, B1_OFF, wro);

    cp_wait1();
    __syncthreads();

    float acc[2][8][4];
    zero_acc(acc);
    run_mma3(acc, sbase, B0_OFF, mbase, nbase, lane);

    __syncthreads();
    store_h(acc, sm, br_, hout, row0, mbase, nbase, g, t, N);
    cp_wait0();
    __syncthreads();

    zero_acc(acc);
    run_mma3(acc, sbase, B1_OFF, mbase, nbase, lane);
    epi(acc, out, row0, mbase, nbase, g, t, nullptr, nullptr, nullptr, N, 1);
}

// ---------------- launch ----------------
extern "C" void kernel_launch(void* const* d_in, const int* in_sizes, int n_in,
                              void* d_out, int out_size) {
    const float* feats = (const float*)d_in[0];
    const float* Wq    = (const float*)d_in[1];
    const float* bq    = (const float*)d_in[2];
    const float* Wk    = (const float*)d_in[3];
    const float* bk    = (const float*)d_in[4];
    const float* Wr    = (const float*)d_in[5];
    const float* br    = (const float*)d_in[6];
    const float* Wro   = (const float*)d_in[7];
    const float* bro   = (const float*)d_in[8];
    const int*   src   = (const int*)d_in[9];
    const int*   dst   = (const int*)d_in[10];

    int N = in_sizes[0] / DIM;   // 50000
    int E = in_sizes[9];         // 800000
    float* out = (float*)d_out;

    __half *hq, *hk;
    float *agg, *h1;
    int *cnt, *off, *cur, *csrc, *bsum;
    cudaGetSymbolAddress((void**)&hq,   g_hq);
    cudaGetSymbolAddress((void**)&hk,   g_hk);
    cudaGetSymbolAddress((void**)&agg,  g_agg);
    cudaGetSymbolAddress((void**)&h1,   g_h1);
    cudaGetSymbolAddress((void**)&cnt,  g_cnt);
    cudaGetSymbolAddress((void**)&off,  g_off);
    cudaGetSymbolAddress((void**)&cur,  g_cur);
    cudaGetSymbolAddress((void**)&csrc, g_csrc);
    cudaGetSymbolAddress((void**)&bsum, g_bsum);

    cudaFuncSetAttribute(gemm_qk3,   cudaFuncAttributeMaxDynamicSharedMemorySize, SMEM_TOTAL);
    cudaFuncSetAttribute(gemm_wr_ro, cudaFuncAttributeMaxDynamicSharedMemorySize, SMEM_TOTAL);

    int gM = (N + 127) / 128;    // 391
    int gAgg = (N * 32 + 255) / 256;
    int nb = (N + SCAN_BLK - 1) / SCAN_BLK;
    int e4 = (E + 3) / 4;

    // fork a second stream for the CSR build (independent of weights/GEMM-L0)
    cudaStream_t s2;
    cudaStreamCreateWithFlags(&s2, cudaStreamNonBlocking);
    cudaEvent_t evF, evJ;
    cudaEventCreateWithFlags(&evF, cudaEventDisableTiming);
    cudaEventCreateWithFlags(&evJ, cudaEventDisableTiming);

    cudaEventRecord(evF, 0);
    cudaStreamWaitEvent(s2, evF, 0);

    // ---- branch A (s2): CSR build ----
    zero_int<<<(N + 255) / 256, 256, 0, s2>>>(cnt, N);
    cnt_kernel<<<(e4 + 255) / 256, 256, 0, s2>>>(dst, E, cnt);
    scan_p1<<<nb, 256, 0, s2>>>(cnt, bsum, N);
    scan_p2<<<1, 32, 0, s2>>>(bsum, off, nb, N);
    scan_p3<<<nb, SCAN_BLK, 0, s2>>>(cnt, bsum, off, cur, N);
    scatter_kernel<<<(e4 + 255) / 256, 256, 0, s2>>>(src, dst, E, cur, csrc);
    cudaEventRecord(evJ, s2);

    // ---- branch B (stream 0): weights + layer-0 Q/K/readout0 GEMM ----
    pack_w<<<9, 1024>>>(Wq, Wk, Wr, Wro);
    gemm_qk3<<<gM, 256, SMEM_TOTAL>>>(feats, 0, 1, 6, bq, bk, bro, hq, hk, out, N);

    // join: agg needs both branches
    cudaStreamWaitEvent(0, evJ, 0);

    agg_csr<<<gAgg, 256>>>(off, csrc, hq, hk, agg, N);
    gemm_wr_ro<<<gM, 256, SMEM_TOTAL>>>(agg, 2, 7, br, h1, out, N);

    gemm_qk3<<<gM, 256, SMEM_TOTAL>>>(h1, 3, 4, -1, bq + 128, bk + 128, nullptr,
                                      hq, hk, nullptr, N);
    agg_csr<<<gAgg, 256>>>(off, csrc, hq, hk, agg, N);
    gemm_wr_ro<<<gM, 256, SMEM_TOTAL>>>(agg, 5, 8, br + 128, nullptr, out, N);

    // NOTE: s2/evF/evJ intentionally not destroyed (stream participated in capture;
    // host-side objects only, no device memory).
}